// round 1
// baseline (speedup 1.0000x reference)
#include <cuda_runtime.h>
#include <math.h>

#define B_    2
#define S_    2048
#define HID_  1024
#define H_    16
#define DK_   64
#define HDK_  1024
#define M_    4096
#define SCALE_ 0.125f
#define NEG_  -1000000000.0f

// Scratch (allocation-free: device globals)
__device__ float g_qh[B_*H_*S_*DK_];   // [B,H,S,DK], SCALE pre-applied
__device__ float g_kh[B_*H_*S_*DK_];   // [B,H,S,DK]
__device__ float g_vh[B_*H_*S_*DK_];   // [B,H,S,DK]
__device__ float g_xh[M_*HDK_];        // [B*S, H*DK] attention out (token-major)

// ---------------------------------------------------------------------------
// SGEMM core: 128x128 C-tile, K-step 16, 256 threads, 8x8 per thread.
// As stored transposed [k][m] with pad 132 to dodge store bank conflicts.
// ---------------------------------------------------------------------------
__device__ __forceinline__ void sgemm_128x128(
    const float* __restrict__ X, const float* __restrict__ W,
    int m0, int n0, int K, int N,
    float acc[8][8], float (*As)[132], float (*Bs)[128])
{
    const int tid   = threadIdx.x;
    const int a_row = tid >> 2;
    const int a_c4  = (tid & 3) << 2;
    const int b_row = tid >> 5;
    const int b_c4  = (tid & 31) << 2;
    const int tx = tid & 15, ty = tid >> 4;

    for (int k0 = 0; k0 < K; k0 += 16) {
        #pragma unroll
        for (int rr = 0; rr < 2; rr++) {
            int r = a_row + rr * 64;
            float4 av = *(const float4*)&X[(size_t)(m0 + r) * K + k0 + a_c4];
            As[a_c4 + 0][r] = av.x;
            As[a_c4 + 1][r] = av.y;
            As[a_c4 + 2][r] = av.z;
            As[a_c4 + 3][r] = av.w;
        }
        #pragma unroll
        for (int rr = 0; rr < 2; rr++) {
            int r = b_row + rr * 8;
            *(float4*)&Bs[r][b_c4] = *(const float4*)&W[(size_t)(k0 + r) * N + n0 + b_c4];
        }
        __syncthreads();
        #pragma unroll
        for (int kk = 0; kk < 16; kk++) {
            float4 a0 = *(const float4*)&As[kk][ty * 8];
            float4 a1 = *(const float4*)&As[kk][ty * 8 + 4];
            float4 b0 = *(const float4*)&Bs[kk][tx * 8];
            float4 b1 = *(const float4*)&Bs[kk][tx * 8 + 4];
            float ra[8] = {a0.x, a0.y, a0.z, a0.w, a1.x, a1.y, a1.z, a1.w};
            float rb[8] = {b0.x, b0.y, b0.z, b0.w, b1.x, b1.y, b1.z, b1.w};
            #pragma unroll
            for (int i = 0; i < 8; i++)
                #pragma unroll
                for (int j = 0; j < 8; j++)
                    acc[i][j] = fmaf(ra[i], rb[j], acc[i][j]);
        }
        __syncthreads();
    }
}

// ---------------------------------------------------------------------------
// Kernel 1: batched Q/K/V projections. z=0:Q (with SCALE), 1:K, 2:V.
// Epilogue writes head-major [B,H,S,DK].
// ---------------------------------------------------------------------------
__global__ __launch_bounds__(256) void proj_kernel(
    const float* __restrict__ q, const float* __restrict__ k, const float* __restrict__ v,
    const float* __restrict__ Wq, const float* __restrict__ bq,
    const float* __restrict__ Wk, const float* __restrict__ bk,
    const float* __restrict__ Wv, const float* __restrict__ bv)
{
    __shared__ float As[16][132];
    __shared__ float Bs[16][128];

    const int z = blockIdx.z;
    const float* X    = (z == 0) ? q  : (z == 1) ? k  : v;
    const float* W    = (z == 0) ? Wq : (z == 1) ? Wk : Wv;
    const float* bias = (z == 0) ? bq : (z == 1) ? bk : bv;
    float*       Y    = (z == 0) ? g_qh : (z == 1) ? g_kh : g_vh;
    const float  osc  = (z == 0) ? SCALE_ : 1.0f;

    const int m0 = blockIdx.y * 128, n0 = blockIdx.x * 128;
    float acc[8][8] = {};
    sgemm_128x128(X, W, m0, n0, HID_, HDK_, acc, As, Bs);

    const int tx = threadIdx.x & 15, ty = threadIdx.x >> 4;
    #pragma unroll
    for (int i = 0; i < 8; i++) {
        int m  = m0 + ty * 8 + i;
        int bb = m >> 11, s = m & 2047;
        #pragma unroll
        for (int j = 0; j < 8; j++) {
            int n  = n0 + tx * 8 + j;
            int hh = n >> 6, dk = n & 63;
            Y[(size_t)(((bb * H_ + hh) * S_) + s) * DK_ + dk] = (acc[i][j] + bias[n]) * osc;
        }
    }
}

// ---------------------------------------------------------------------------
// Kernel 2: fused flash attention. Block = 64 q-rows of one (b,h).
// 256 threads as 16x16: thread owns 4 q-rows x 4 cols (k-cols for S, dk for O).
// Smem: Qs[64][64], KS[64][68] (K^T during score pass, P after), Vs[64][64].
// ---------------------------------------------------------------------------
__global__ __launch_bounds__(256) void attn_kernel(
    const float* __restrict__ attn_bias, const int* __restrict__ mask)
{
    extern __shared__ float sm[];
    float (*Qs)[64] = (float(*)[64])sm;                   // 4096 floats
    float (*KS)[68] = (float(*)[68])(sm + 4096);          // 4352 floats (K^T, then P)
    float (*Vs)[64] = (float(*)[64])(sm + 4096 + 4352);   // 4096 floats

    const int tid = threadIdx.x;
    const int tx = tid & 15, ty = tid >> 4;
    const int tx4 = tx * 4, ty4 = ty * 4;
    const int q0 = blockIdx.x * 64;
    const int h  = blockIdx.y, b = blockIdx.z;

    const float* qbase  = g_qh + (size_t)((b * H_ + h) * S_) * DK_;
    const float* kbase  = g_kh + (size_t)((b * H_ + h) * S_) * DK_;
    const float* vbase  = g_vh + (size_t)((b * H_ + h) * S_) * DK_;
    const float* biasb  = attn_bias + (size_t)((b * H_ + h) * S_ + q0) * S_;
    const int*   maskb  = mask + b * S_;

    // Load Q tile (scale pre-applied)
    #pragma unroll
    for (int it = 0; it < 4; it++) {
        int i = tid + it * 256;
        int r = i >> 4, c4 = (i & 15) << 2;
        *(float4*)&Qs[r][c4] = *(const float4*)&qbase[(size_t)(q0 + r) * DK_ + c4];
    }

    float o[4][4] = {};
    float mrow[4] = {-INFINITY, -INFINITY, -INFINITY, -INFINITY};
    float lrow[4] = {};

    for (int k0 = 0; k0 < S_; k0 += 64) {
        __syncthreads();  // prior O-pass done with KS/Vs
        // Load K^T (KS[d][kj]) and V (Vs[kj][d])
        #pragma unroll
        for (int it = 0; it < 4; it++) {
            int i = tid + it * 256;
            int r = i >> 4, c4 = (i & 15) << 2;
            float4 kv = *(const float4*)&kbase[(size_t)(k0 + r) * DK_ + c4];
            KS[c4 + 0][r] = kv.x;
            KS[c4 + 1][r] = kv.y;
            KS[c4 + 2][r] = kv.z;
            KS[c4 + 3][r] = kv.w;
            *(float4*)&Vs[r][c4] = *(const float4*)&vbase[(size_t)(k0 + r) * DK_ + c4];
        }
        __syncthreads();

        // Scores: sv[i][j] = Q[ty4+i][:] . K[k0+tx4+j][:]
        float sv[4][4] = {};
        #pragma unroll 8
        for (int d = 0; d < 64; d++) {
            float a0 = Qs[ty4 + 0][d];
            float a1 = Qs[ty4 + 1][d];
            float a2 = Qs[ty4 + 2][d];
            float a3 = Qs[ty4 + 3][d];
            float4 kb = *(const float4*)&KS[d][tx4];
            sv[0][0] = fmaf(a0, kb.x, sv[0][0]); sv[0][1] = fmaf(a0, kb.y, sv[0][1]);
            sv[0][2] = fmaf(a0, kb.z, sv[0][2]); sv[0][3] = fmaf(a0, kb.w, sv[0][3]);
            sv[1][0] = fmaf(a1, kb.x, sv[1][0]); sv[1][1] = fmaf(a1, kb.y, sv[1][1]);
            sv[1][2] = fmaf(a1, kb.z, sv[1][2]); sv[1][3] = fmaf(a1, kb.w, sv[1][3]);
            sv[2][0] = fmaf(a2, kb.x, sv[2][0]); sv[2][1] = fmaf(a2, kb.y, sv[2][1]);
            sv[2][2] = fmaf(a2, kb.z, sv[2][2]); sv[2][3] = fmaf(a2, kb.w, sv[2][3]);
            sv[3][0] = fmaf(a3, kb.x, sv[3][0]); sv[3][1] = fmaf(a3, kb.y, sv[3][1]);
            sv[3][2] = fmaf(a3, kb.z, sv[3][2]); sv[3][3] = fmaf(a3, kb.w, sv[3][3]);
        }

        // k-mask + bias (reference: where(mask==0, NEG, s) + bias)
        int4 km = *(const int4*)&maskb[k0 + tx4];
        #pragma unroll
        for (int i = 0; i < 4; i++) {
            float4 bb4 = *(const float4*)&biasb[(size_t)(ty4 + i) * S_ + k0 + tx4];
            sv[i][0] = (km.x ? sv[i][0] : NEG_) + bb4.x;
            sv[i][1] = (km.y ? sv[i][1] : NEG_) + bb4.y;
            sv[i][2] = (km.z ? sv[i][2] : NEG_) + bb4.z;
            sv[i][3] = (km.w ? sv[i][3] : NEG_) + bb4.w;
        }

        __syncthreads();  // all threads done reading K^T; KS becomes P

        // Online softmax update (row reductions over 16 tx lanes via xor-shuffle)
        #pragma unroll
        for (int i = 0; i < 4; i++) {
            float mx = fmaxf(fmaxf(sv[i][0], sv[i][1]), fmaxf(sv[i][2], sv[i][3]));
            mx = fmaxf(mx, __shfl_xor_sync(0xffffffffu, mx, 1));
            mx = fmaxf(mx, __shfl_xor_sync(0xffffffffu, mx, 2));
            mx = fmaxf(mx, __shfl_xor_sync(0xffffffffu, mx, 4));
            mx = fmaxf(mx, __shfl_xor_sync(0xffffffffu, mx, 8));
            float mnew = fmaxf(mrow[i], mx);
            float fac  = __expf(mrow[i] - mnew);
            mrow[i] = mnew;
            float ps = 0.f;
            #pragma unroll
            for (int j = 0; j < 4; j++) {
                float p = __expf(sv[i][j] - mnew);
                sv[i][j] = p;
                ps += p;
            }
            ps += __shfl_xor_sync(0xffffffffu, ps, 1);
            ps += __shfl_xor_sync(0xffffffffu, ps, 2);
            ps += __shfl_xor_sync(0xffffffffu, ps, 4);
            ps += __shfl_xor_sync(0xffffffffu, ps, 8);
            lrow[i] = lrow[i] * fac + ps;
            #pragma unroll
            for (int j = 0; j < 4; j++) o[i][j] *= fac;
            *(float4*)&KS[ty4 + i][tx4] = make_float4(sv[i][0], sv[i][1], sv[i][2], sv[i][3]);
        }
        __syncthreads();

        // O += P @ V
        #pragma unroll 8
        for (int j = 0; j < 64; j++) {
            float p0 = KS[ty4 + 0][j];
            float p1 = KS[ty4 + 1][j];
            float p2 = KS[ty4 + 2][j];
            float p3 = KS[ty4 + 3][j];
            float4 vv = *(const float4*)&Vs[j][tx4];
            o[0][0] = fmaf(p0, vv.x, o[0][0]); o[0][1] = fmaf(p0, vv.y, o[0][1]);
            o[0][2] = fmaf(p0, vv.z, o[0][2]); o[0][3] = fmaf(p0, vv.w, o[0][3]);
            o[1][0] = fmaf(p1, vv.x, o[1][0]); o[1][1] = fmaf(p1, vv.y, o[1][1]);
            o[1][2] = fmaf(p1, vv.z, o[1][2]); o[1][3] = fmaf(p1, vv.w, o[1][3]);
            o[2][0] = fmaf(p2, vv.x, o[2][0]); o[2][1] = fmaf(p2, vv.y, o[2][1]);
            o[2][2] = fmaf(p2, vv.z, o[2][2]); o[2][3] = fmaf(p2, vv.w, o[2][3]);
            o[3][0] = fmaf(p3, vv.x, o[3][0]); o[3][1] = fmaf(p3, vv.y, o[3][1]);
            o[3][2] = fmaf(p3, vv.z, o[3][2]); o[3][3] = fmaf(p3, vv.w, o[3][3]);
        }
    }

    // Epilogue: normalize, apply q-mask, write token-major xh[b*S+s][h*DK+dk]
    #pragma unroll
    for (int i = 0; i < 4; i++) {
        int r = q0 + ty4 + i;
        float qm  = (maskb[r] != 0) ? 1.0f : 0.0f;
        float inv = qm / lrow[i];
        float4 o4 = make_float4(o[i][0] * inv, o[i][1] * inv, o[i][2] * inv, o[i][3] * inv);
        *(float4*)&g_xh[((size_t)(b * S_ + r)) * HDK_ + h * DK_ + tx4] = o4;
    }
}

// ---------------------------------------------------------------------------
// Kernel 3: output projection  out = xh @ Wo + bo
// ---------------------------------------------------------------------------
__global__ __launch_bounds__(256) void out_kernel(
    const float* __restrict__ Wo, const float* __restrict__ bo, float* __restrict__ out)
{
    __shared__ float As[16][132];
    __shared__ float Bs[16][128];

    const int m0 = blockIdx.y * 128, n0 = blockIdx.x * 128;
    float acc[8][8] = {};
    sgemm_128x128(g_xh, Wo, m0, n0, HDK_, HDK_, acc, As, Bs);

    const int tx = threadIdx.x & 15, ty = threadIdx.x >> 4;
    #pragma unroll
    for (int i = 0; i < 8; i++) {
        int m = m0 + ty * 8 + i;
        #pragma unroll
        for (int j = 0; j < 8; j++) {
            int n = n0 + tx * 8 + j;
            out[(size_t)m * HDK_ + n] = acc[i][j] + bo[n];
        }
    }
}

// ---------------------------------------------------------------------------
extern "C" void kernel_launch(void* const* d_in, const int* in_sizes, int n_in,
                              void* d_out, int out_size)
{
    const float* q         = (const float*)d_in[0];
    const float* k         = (const float*)d_in[1];
    const float* v         = (const float*)d_in[2];
    const float* attn_bias = (const float*)d_in[3];
    const int*   mask      = (const int*)  d_in[4];
    const float* Wq        = (const float*)d_in[5];
    const float* bq        = (const float*)d_in[6];
    const float* Wk        = (const float*)d_in[7];
    const float* bk        = (const float*)d_in[8];
    const float* Wv        = (const float*)d_in[9];
    const float* bv        = (const float*)d_in[10];
    const float* Wo        = (const float*)d_in[11];
    const float* bo        = (const float*)d_in[12];
    float* out = (float*)d_out;

    const int attn_smem = (4096 + 4352 + 4096) * (int)sizeof(float);  // 50176 B
    cudaFuncSetAttribute(attn_kernel, cudaFuncAttributeMaxDynamicSharedMemorySize, attn_smem);

    dim3 pgrid(HDK_ / 128, M_ / 128, 3);
    proj_kernel<<<pgrid, 256>>>(q, k, v, Wq, bq, Wk, bk, Wv, bv);

    dim3 agrid(S_ / 64, H_, B_);
    attn_kernel<<<agrid, 256, attn_smem>>>(attn_bias, mask);

    dim3 ogrid(HDK_ / 128, M_ / 128);
    out_kernel<<<ogrid, 256>>>(Wo, bo, out);
}

// round 3
// speedup vs baseline: 1.2817x; 1.2817x over previous
#include <cuda_runtime.h>
#include <cuda_bf16.h>
#include <math.h>
#include <stdint.h>

#define B_    2
#define S_    2048
#define HID_  1024
#define H_    16
#define DK_   64
#define HDK_  1024
#define M_    4096
#define SCALE_ 0.125f
#define NEG_  -1000000000.0f

// Scratch (allocation-free device globals)
__device__ float g_qh[B_*H_*S_*DK_];   // [B,H,S,DK], SCALE pre-applied
__device__ float g_kh[B_*H_*S_*DK_];
__device__ float g_vh[B_*H_*S_*DK_];
__device__ float g_xh[M_*HDK_];        // attention out, token-major
__device__ __nv_bfloat16 g_wh[4u*HID_*HDK_];  // W hi, [g][k][n] (same layout as W)
__device__ __nv_bfloat16 g_wl[4u*HID_*HDK_];  // W lo

// ---------------------------------------------------------------------------
// sm_80-class PTX helpers (no 'a'-suffix features: harness targets compute_103)
// ---------------------------------------------------------------------------
__device__ __forceinline__ uint32_t smem_u32(const void* p) {
    uint32_t a;
    asm("{ .reg .u64 t; cvta.to.shared.u64 t, %1; cvt.u32.u64 %0, t; }"
        : "=r"(a) : "l"(p));
    return a;
}

__device__ __forceinline__ void lds4(uint32_t* r, uint32_t addr) {
    asm volatile("ldmatrix.sync.aligned.m8n8.x4.shared.b16 {%0,%1,%2,%3}, [%4];"
                 : "=r"(r[0]), "=r"(r[1]), "=r"(r[2]), "=r"(r[3]) : "r"(addr));
}
__device__ __forceinline__ void lds4t(uint32_t* r, uint32_t addr) {
    asm volatile("ldmatrix.sync.aligned.m8n8.x4.trans.shared.b16 {%0,%1,%2,%3}, [%4];"
                 : "=r"(r[0]), "=r"(r[1]), "=r"(r[2]), "=r"(r[3]) : "r"(addr));
}
__device__ __forceinline__ void mma16816(float* d, const uint32_t* a, const uint32_t* b) {
    asm volatile(
        "mma.sync.aligned.m16n8k16.row.col.f32.bf16.bf16.f32 "
        "{%0,%1,%2,%3}, {%4,%5,%6,%7}, {%8,%9}, {%0,%1,%2,%3};"
        : "+f"(d[0]), "+f"(d[1]), "+f"(d[2]), "+f"(d[3])
        : "r"(a[0]), "r"(a[1]), "r"(a[2]), "r"(a[3]), "r"(b[0]), "r"(b[1]));
}
#define CP_ASYNC16(dst, src) \
    asm volatile("cp.async.cg.shared.global [%0], [%1], 16;" :: "r"(dst), "l"(src))
#define CP_COMMIT() asm volatile("cp.async.commit_group;" ::: "memory")
#define CP_WAIT0()  asm volatile("cp.async.wait_group 0;" ::: "memory")

__device__ __forceinline__ void split2(float a, float b, uint32_t& hi, uint32_t& lo) {
    __nv_bfloat16 ah = __float2bfloat16(a);
    __nv_bfloat16 bh = __float2bfloat16(b);
    __nv_bfloat16 al = __float2bfloat16(a - __bfloat162float(ah));
    __nv_bfloat16 bl = __float2bfloat16(b - __bfloat162float(bh));
    hi = (uint32_t)__bfloat16_as_ushort(ah) | ((uint32_t)__bfloat16_as_ushort(bh) << 16);
    lo = (uint32_t)__bfloat16_as_ushort(al) | ((uint32_t)__bfloat16_as_ushort(bl) << 16);
}

// ---------------------------------------------------------------------------
// Weight hi/lo split (no transpose: ldmatrix.trans consumes [k][n] directly)
// ---------------------------------------------------------------------------
__global__ __launch_bounds__(256) void wsplit_kernel(
    const float* __restrict__ Wq, const float* __restrict__ Wk,
    const float* __restrict__ Wv, const float* __restrict__ Wo)
{
    const int g = blockIdx.y;
    const float* W = (g == 0) ? Wq : (g == 1) ? Wk : (g == 2) ? Wv : Wo;
    const int idx = blockIdx.x * 256 + threadIdx.x;     // float4 index, 262144 total
    float4 x = ((const float4*)W)[idx];
    uint32_t h0, l0, h1, l1;
    split2(x.x, x.y, h0, l0);
    split2(x.z, x.w, h1, l1);
    uint2* WH = (uint2*)(g_wh + (size_t)g * HID_ * HDK_);
    uint2* WL = (uint2*)(g_wl + (size_t)g * HID_ * HDK_);
    WH[idx] = make_uint2(h0, h1);
    WL[idx] = make_uint2(l0, l1);
}

// ---------------------------------------------------------------------------
// bf16x3 HMMA GEMM core. CTA 128x128, 8 warps (4m x 2n), warp 32x64.
// K-chunk 32, 2-stage smem. Smem per stage:
//   AH [128][40] bf16 (10240B) | AL (10240B) | BH [32][136] (8704B) | BL (8704B)
// ---------------------------------------------------------------------------
#define A_PAD 40
#define B_PAD 136
#define OFF_AL 10240
#define OFF_BH 20480
#define OFF_BL 29184
#define STAGE_ 37888
#define GSM_BYTES (2 * STAGE_)

__device__ __forceinline__ void ldgA(const float* __restrict__ X, int m0, int k0,
                                     int tid, float4* pa) {
    const int r = tid >> 1, cb = (tid & 1) * 16;
    const float* src = X + (size_t)(m0 + r) * HID_ + k0 + cb;
    pa[0] = *(const float4*)(src);
    pa[1] = *(const float4*)(src + 4);
    pa[2] = *(const float4*)(src + 8);
    pa[3] = *(const float4*)(src + 12);
}

__device__ __forceinline__ void stsA(char* aHp, char* aLp, int tid, const float4* pa) {
    const int r = tid >> 1, cb = (tid & 1) * 16;
    uint32_t hi[8], lo[8];
    #pragma unroll
    for (int i = 0; i < 4; i++) {
        split2(pa[i].x, pa[i].y, hi[2*i],   lo[2*i]);
        split2(pa[i].z, pa[i].w, hi[2*i+1], lo[2*i+1]);
    }
    const uint32_t off = (uint32_t)(r * A_PAD + cb) * 2;
    *(uint4*)(aHp + off)      = make_uint4(hi[0], hi[1], hi[2], hi[3]);
    *(uint4*)(aHp + off + 16) = make_uint4(hi[4], hi[5], hi[6], hi[7]);
    *(uint4*)(aLp + off)      = make_uint4(lo[0], lo[1], lo[2], lo[3]);
    *(uint4*)(aLp + off + 16) = make_uint4(lo[4], lo[5], lo[6], lo[7]);
}

__device__ __forceinline__ void cpB(uint32_t bH, uint32_t bL,
                                    const __nv_bfloat16* __restrict__ WHp,
                                    const __nv_bfloat16* __restrict__ WLp,
                                    int n0, int k0, int tid) {
    #pragma unroll
    for (int i = 0; i < 2; i++) {
        const int q = tid + i * 256;              // 512 16B-chunks per matrix
        const int row = q >> 4, c8 = (q & 15) * 8;
        const size_t g = (size_t)(k0 + row) * HDK_ + n0 + c8;
        const uint32_t d = (uint32_t)(row * B_PAD + c8) * 2;
        CP_ASYNC16(bH + d, WHp + g);
        CP_ASYNC16(bL + d, WLp + g);
    }
}

// acc[2][8][4] per warp (warp tile 32x64)
__device__ __forceinline__ void gemm_main(
    const float* __restrict__ X,
    const __nv_bfloat16* __restrict__ WH, const __nv_bfloat16* __restrict__ WL,
    int m0, int n0, char* smc, uint32_t smb, float acc[2][8][4])
{
    const int tid  = threadIdx.x;
    const int lane = tid & 31;
    const int warp = tid >> 5;
    const int m0w  = (warp >> 1) * 32;
    const int n0w  = (warp & 1) * 64;
    const int arow = m0w + (lane & 15);
    const int acol = (lane >> 4) * 8;
    const int brow = lane & 15;
    const int bcol = n0w + (lane >> 4) * 8;

    float4 pa[4];

    // Prologue: chunk 0 -> stage 0
    ldgA(X, m0, 0, tid, pa);
    cpB(smb + OFF_BH, smb + OFF_BL, WH, WL, n0, 0, tid);
    CP_COMMIT();
    stsA(smc, smc + OFF_AL, tid, pa);
    CP_WAIT0();
    __syncthreads();

    for (int c = 0; c < 32; ++c) {
        const int s = c & 1;
        const uint32_t sb = smb + s * STAGE_;
        char* scn = smc + (s ^ 1) * STAGE_;

        if (c + 1 < 32) {
            ldgA(X, m0, (c + 1) * 32, tid, pa);
            cpB(smb + (s ^ 1) * STAGE_ + OFF_BH, smb + (s ^ 1) * STAGE_ + OFF_BL,
                WH, WL, n0, (c + 1) * 32, tid);
            CP_COMMIT();
        }

        // Compute chunk c from stage s
        #pragma unroll
        for (int ks = 0; ks < 2; ++ks) {
            uint32_t ah[2][4], al[2][4];
            #pragma unroll
            for (int mf = 0; mf < 2; ++mf) {
                const uint32_t aoff = (uint32_t)((arow + mf * 16) * A_PAD + ks * 16 + acol) * 2;
                lds4(ah[mf], sb + aoff);
                lds4(al[mf], sb + OFF_AL + aoff);
            }
            #pragma unroll
            for (int np = 0; np < 4; ++np) {
                const uint32_t boff = (uint32_t)((ks * 16 + brow) * B_PAD + bcol + np * 16) * 2;
                uint32_t bh[4], bl[4];
                lds4t(bh, sb + OFF_BH + boff);
                lds4t(bl, sb + OFF_BL + boff);
                #pragma unroll
                for (int mf = 0; mf < 2; ++mf) {
                    mma16816(acc[mf][2*np],   ah[mf], bh);
                    mma16816(acc[mf][2*np+1], ah[mf], bh + 2);
                    mma16816(acc[mf][2*np],   ah[mf], bl);
                    mma16816(acc[mf][2*np+1], ah[mf], bl + 2);
                    mma16816(acc[mf][2*np],   al[mf], bh);
                    mma16816(acc[mf][2*np+1], al[mf], bh + 2);
                }
            }
        }

        if (c + 1 < 32) stsA(scn, scn + OFF_AL, tid, pa);
        CP_WAIT0();
        __syncthreads();
    }
}

// ---------------------------------------------------------------------------
// Projection GEMMs (z = 0:Q scaled, 1:K, 2:V) -> head-major scratch
// ---------------------------------------------------------------------------
__global__ __launch_bounds__(256, 1) void proj_tc_kernel(
    const float* __restrict__ q, const float* __restrict__ k, const float* __restrict__ v,
    const float* __restrict__ bq, const float* __restrict__ bk, const float* __restrict__ bv)
{
    extern __shared__ char smc[];
    const uint32_t smb = smem_u32(smc);

    const int z = blockIdx.z;
    const float* X    = (z == 0) ? q  : (z == 1) ? k  : v;
    const float* bias = (z == 0) ? bq : (z == 1) ? bk : bv;
    const __nv_bfloat16* WH = g_wh + (size_t)z * HID_ * HDK_;
    const __nv_bfloat16* WL = g_wl + (size_t)z * HID_ * HDK_;
    float* Y = (z == 0) ? g_qh : (z == 1) ? g_kh : g_vh;
    const float osc = (z == 0) ? SCALE_ : 1.0f;

    const int m0 = blockIdx.y * 128, n0 = blockIdx.x * 128;
    float acc[2][8][4] = {};
    gemm_main(X, WH, WL, m0, n0, smc, smb, acc);

    const int lane = threadIdx.x & 31, warp = threadIdx.x >> 5;
    const int m0w = (warp >> 1) * 32, n0w = (warp & 1) * 64;
    #pragma unroll
    for (int mf = 0; mf < 2; ++mf) {
        #pragma unroll
        for (int nf = 0; nf < 8; ++nf) {
            const int mr = m0 + m0w + mf * 16 + (lane >> 2);
            const int nn = n0 + n0w + nf * 8 + (lane & 3) * 2;
            const int hh = nn >> 6, dk = nn & 63;
            const float b0 = bias[nn], b1 = bias[nn + 1];
            {
                const int bb = mr >> 11, ss = mr & 2047;
                float2 o = make_float2((acc[mf][nf][0] + b0) * osc,
                                       (acc[mf][nf][1] + b1) * osc);
                *(float2*)&Y[(((size_t)bb * H_ + hh) * S_ + ss) * DK_ + dk] = o;
            }
            {
                const int mr2 = mr + 8;
                const int bb = mr2 >> 11, ss = mr2 & 2047;
                float2 o = make_float2((acc[mf][nf][2] + b0) * osc,
                                       (acc[mf][nf][3] + b1) * osc);
                *(float2*)&Y[(((size_t)bb * H_ + hh) * S_ + ss) * DK_ + dk] = o;
            }
        }
    }
}

// ---------------------------------------------------------------------------
// Output GEMM: out = xh @ Wo + bo
// ---------------------------------------------------------------------------
__global__ __launch_bounds__(256, 1) void out_tc_kernel(
    const float* __restrict__ bo, float* __restrict__ out)
{
    extern __shared__ char smc[];
    const uint32_t smb = smem_u32(smc);

    const __nv_bfloat16* WH = g_wh + (size_t)3 * HID_ * HDK_;
    const __nv_bfloat16* WL = g_wl + (size_t)3 * HID_ * HDK_;

    const int m0 = blockIdx.y * 128, n0 = blockIdx.x * 128;
    float acc[2][8][4] = {};
    gemm_main(g_xh, WH, WL, m0, n0, smc, smb, acc);

    const int lane = threadIdx.x & 31, warp = threadIdx.x >> 5;
    const int m0w = (warp >> 1) * 32, n0w = (warp & 1) * 64;
    #pragma unroll
    for (int mf = 0; mf < 2; ++mf) {
        #pragma unroll
        for (int nf = 0; nf < 8; ++nf) {
            const int mr = m0 + m0w + mf * 16 + (lane >> 2);
            const int nn = n0 + n0w + nf * 8 + (lane & 3) * 2;
            const float b0 = bo[nn], b1 = bo[nn + 1];
            *(float2*)&out[(size_t)mr * HDK_ + nn] =
                make_float2(acc[mf][nf][0] + b0, acc[mf][nf][1] + b1);
            *(float2*)&out[(size_t)(mr + 8) * HDK_ + nn] =
                make_float2(acc[mf][nf][2] + b0, acc[mf][nf][3] + b1);
        }
    }
}

// ---------------------------------------------------------------------------
// Fused flash attention (SIMT fp32, unchanged from R1)
// ---------------------------------------------------------------------------
__global__ __launch_bounds__(256) void attn_kernel(
    const float* __restrict__ attn_bias, const int* __restrict__ mask)
{
    extern __shared__ float smf[];
    float (*Qs)[64] = (float(*)[64])smf;
    float (*KS)[68] = (float(*)[68])(smf + 4096);
    float (*Vs)[64] = (float(*)[64])(smf + 4096 + 4352);

    const int tid = threadIdx.x;
    const int tx = tid & 15, ty = tid >> 4;
    const int tx4 = tx * 4, ty4 = ty * 4;
    const int q0 = blockIdx.x * 64;
    const int h  = blockIdx.y, b = blockIdx.z;

    const float* qbase  = g_qh + (size_t)((b * H_ + h) * S_) * DK_;
    const float* kbase  = g_kh + (size_t)((b * H_ + h) * S_) * DK_;
    const float* vbase  = g_vh + (size_t)((b * H_ + h) * S_) * DK_;
    const float* biasb  = attn_bias + (size_t)((b * H_ + h) * S_ + q0) * S_;
    const int*   maskb  = mask + b * S_;

    #pragma unroll
    for (int it = 0; it < 4; it++) {
        int i = tid + it * 256;
        int r = i >> 4, c4 = (i & 15) << 2;
        *(float4*)&Qs[r][c4] = *(const float4*)&qbase[(size_t)(q0 + r) * DK_ + c4];
    }

    float o[4][4] = {};
    float mrow[4] = {-INFINITY, -INFINITY, -INFINITY, -INFINITY};
    float lrow[4] = {};

    for (int k0 = 0; k0 < S_; k0 += 64) {
        __syncthreads();
        #pragma unroll
        for (int it = 0; it < 4; it++) {
            int i = tid + it * 256;
            int r = i >> 4, c4 = (i & 15) << 2;
            float4 kv = *(const float4*)&kbase[(size_t)(k0 + r) * DK_ + c4];
            KS[c4 + 0][r] = kv.x;
            KS[c4 + 1][r] = kv.y;
            KS[c4 + 2][r] = kv.z;
            KS[c4 + 3][r] = kv.w;
            *(float4*)&Vs[r][c4] = *(const float4*)&vbase[(size_t)(k0 + r) * DK_ + c4];
        }
        __syncthreads();

        float sv[4][4] = {};
        #pragma unroll 8
        for (int d = 0; d < 64; d++) {
            float a0 = Qs[ty4 + 0][d];
            float a1 = Qs[ty4 + 1][d];
            float a2 = Qs[ty4 + 2][d];
            float a3 = Qs[ty4 + 3][d];
            float4 kb = *(const float4*)&KS[d][tx4];
            sv[0][0] = fmaf(a0, kb.x, sv[0][0]); sv[0][1] = fmaf(a0, kb.y, sv[0][1]);
            sv[0][2] = fmaf(a0, kb.z, sv[0][2]); sv[0][3] = fmaf(a0, kb.w, sv[0][3]);
            sv[1][0] = fmaf(a1, kb.x, sv[1][0]); sv[1][1] = fmaf(a1, kb.y, sv[1][1]);
            sv[1][2] = fmaf(a1, kb.z, sv[1][2]); sv[1][3] = fmaf(a1, kb.w, sv[1][3]);
            sv[2][0] = fmaf(a2, kb.x, sv[2][0]); sv[2][1] = fmaf(a2, kb.y, sv[2][1]);
            sv[2][2] = fmaf(a2, kb.z, sv[2][2]); sv[2][3] = fmaf(a2, kb.w, sv[2][3]);
            sv[3][0] = fmaf(a3, kb.x, sv[3][0]); sv[3][1] = fmaf(a3, kb.y, sv[3][1]);
            sv[3][2] = fmaf(a3, kb.z, sv[3][2]); sv[3][3] = fmaf(a3, kb.w, sv[3][3]);
        }

        int4 km = *(const int4*)&maskb[k0 + tx4];
        #pragma unroll
        for (int i = 0; i < 4; i++) {
            float4 bb4 = *(const float4*)&biasb[(size_t)(ty4 + i) * S_ + k0 + tx4];
            sv[i][0] = (km.x ? sv[i][0] : NEG_) + bb4.x;
            sv[i][1] = (km.y ? sv[i][1] : NEG_) + bb4.y;
            sv[i][2] = (km.z ? sv[i][2] : NEG_) + bb4.z;
            sv[i][3] = (km.w ? sv[i][3] : NEG_) + bb4.w;
        }

        __syncthreads();

        #pragma unroll
        for (int i = 0; i < 4; i++) {
            float mx = fmaxf(fmaxf(sv[i][0], sv[i][1]), fmaxf(sv[i][2], sv[i][3]));
            mx = fmaxf(mx, __shfl_xor_sync(0xffffffffu, mx, 1));
            mx = fmaxf(mx, __shfl_xor_sync(0xffffffffu, mx, 2));
            mx = fmaxf(mx, __shfl_xor_sync(0xffffffffu, mx, 4));
            mx = fmaxf(mx, __shfl_xor_sync(0xffffffffu, mx, 8));
            float mnew = fmaxf(mrow[i], mx);
            float fac  = __expf(mrow[i] - mnew);
            mrow[i] = mnew;
            float ps = 0.f;
            #pragma unroll
            for (int j = 0; j < 4; j++) {
                float p = __expf(sv[i][j] - mnew);
                sv[i][j] = p;
                ps += p;
            }
            ps += __shfl_xor_sync(0xffffffffu, ps, 1);
            ps += __shfl_xor_sync(0xffffffffu, ps, 2);
            ps += __shfl_xor_sync(0xffffffffu, ps, 4);
            ps += __shfl_xor_sync(0xffffffffu, ps, 8);
            lrow[i] = lrow[i] * fac + ps;
            #pragma unroll
            for (int j = 0; j < 4; j++) o[i][j] *= fac;
            *(float4*)&KS[ty4 + i][tx4] = make_float4(sv[i][0], sv[i][1], sv[i][2], sv[i][3]);
        }
        __syncthreads();

        #pragma unroll 8
        for (int j = 0; j < 64; j++) {
            float p0 = KS[ty4 + 0][j];
            float p1 = KS[ty4 + 1][j];
            float p2 = KS[ty4 + 2][j];
            float p3 = KS[ty4 + 3][j];
            float4 vv = *(const float4*)&Vs[j][tx4];
            o[0][0] = fmaf(p0, vv.x, o[0][0]); o[0][1] = fmaf(p0, vv.y, o[0][1]);
            o[0][2] = fmaf(p0, vv.z, o[0][2]); o[0][3] = fmaf(p0, vv.w, o[0][3]);
            o[1][0] = fmaf(p1, vv.x, o[1][0]); o[1][1] = fmaf(p1, vv.y, o[1][1]);
            o[1][2] = fmaf(p1, vv.z, o[1][2]); o[1][3] = fmaf(p1, vv.w, o[1][3]);
            o[2][0] = fmaf(p2, vv.x, o[2][0]); o[2][1] = fmaf(p2, vv.y, o[2][1]);
            o[2][2] = fmaf(p2, vv.z, o[2][2]); o[2][3] = fmaf(p2, vv.w, o[2][3]);
            o[3][0] = fmaf(p3, vv.x, o[3][0]); o[3][1] = fmaf(p3, vv.y, o[3][1]);
            o[3][2] = fmaf(p3, vv.z, o[3][2]); o[3][3] = fmaf(p3, vv.w, o[3][3]);
        }
    }

    #pragma unroll
    for (int i = 0; i < 4; i++) {
        int r = q0 + ty4 + i;
        float qm  = (maskb[r] != 0) ? 1.0f : 0.0f;
        float inv = qm / lrow[i];
        float4 o4 = make_float4(o[i][0] * inv, o[i][1] * inv, o[i][2] * inv, o[i][3] * inv);
        *(float4*)&g_xh[((size_t)(b * S_ + r)) * HDK_ + h * DK_ + tx4] = o4;
    }
}

// ---------------------------------------------------------------------------
extern "C" void kernel_launch(void* const* d_in, const int* in_sizes, int n_in,
                              void* d_out, int out_size)
{
    const float* q         = (const float*)d_in[0];
    const float* k         = (const float*)d_in[1];
    const float* v         = (const float*)d_in[2];
    const float* attn_bias = (const float*)d_in[3];
    const int*   mask      = (const int*)  d_in[4];
    const float* Wq        = (const float*)d_in[5];
    const float* bq        = (const float*)d_in[6];
    const float* Wk        = (const float*)d_in[7];
    const float* bk        = (const float*)d_in[8];
    const float* Wv        = (const float*)d_in[9];
    const float* bv        = (const float*)d_in[10];
    const float* Wo        = (const float*)d_in[11];
    const float* bo        = (const float*)d_in[12];
    float* out = (float*)d_out;

    static int configured = 0;
    if (!configured) {
        cudaFuncSetAttribute(proj_tc_kernel, cudaFuncAttributeMaxDynamicSharedMemorySize, GSM_BYTES);
        cudaFuncSetAttribute(out_tc_kernel,  cudaFuncAttributeMaxDynamicSharedMemorySize, GSM_BYTES);
        cudaFuncSetAttribute(attn_kernel,    cudaFuncAttributeMaxDynamicSharedMemorySize,
                             (4096 + 4352 + 4096) * (int)sizeof(float));
        configured = 1;
    }

    // 1. Weight hi/lo split (elementwise, layout preserved)
    wsplit_kernel<<<dim3(HID_ * HDK_ / 4 / 256, 4), 256>>>(Wq, Wk, Wv, Wo);

    // 2. Q/K/V projections (HMMA bf16x3)
    proj_tc_kernel<<<dim3(HDK_ / 128, M_ / 128, 3), 256, GSM_BYTES>>>(q, k, v, bq, bk, bv);

    // 3. Fused attention (SIMT fp32)
    const int attn_smem = (4096 + 4352 + 4096) * (int)sizeof(float);
    attn_kernel<<<dim3(S_ / 64, H_, B_), 256, attn_smem>>>(attn_bias, mask);

    // 4. Output projection (HMMA bf16x3)
    out_tc_kernel<<<dim3(HDK_ / 128, M_ / 128), 256, GSM_BYTES>>>(bo, out);
}

// round 4
// speedup vs baseline: 1.9795x; 1.5445x over previous
#include <cuda_runtime.h>
#include <cuda_bf16.h>
#include <math.h>
#include <stdint.h>

#define B_    2
#define S_    2048
#define HID_  1024
#define H_    16
#define DK_   64
#define HDK_  1024
#define M_    4096
#define SCALE_ 0.125f
#define NEG_  -1000000000.0f

// Scratch (allocation-free device globals)
__device__ __nv_bfloat16 g_qhi[B_*H_*S_*DK_], g_qlo[B_*H_*S_*DK_];
__device__ __nv_bfloat16 g_khi[B_*H_*S_*DK_], g_klo[B_*H_*S_*DK_];
__device__ __nv_bfloat16 g_vhi[B_*H_*S_*DK_], g_vlo[B_*H_*S_*DK_];
__device__ float g_xh[M_*HDK_];                 // attention out, token-major
__device__ float g_maskf[B_*S_];                // mask as float 0/1
__device__ __nv_bfloat16 g_wh[4u*HID_*HDK_];    // W hi, [g][k][n]
__device__ __nv_bfloat16 g_wl[4u*HID_*HDK_];    // W lo

// ---------------------------------------------------------------------------
// sm_80-class PTX helpers (harness targets compute_103: no 'a' features)
// ---------------------------------------------------------------------------
__device__ __forceinline__ uint32_t smem_u32(const void* p) {
    uint32_t a;
    asm("{ .reg .u64 t; cvta.to.shared.u64 t, %1; cvt.u32.u64 %0, t; }"
        : "=r"(a) : "l"(p));
    return a;
}
__device__ __forceinline__ void lds4(uint32_t* r, uint32_t addr) {
    asm volatile("ldmatrix.sync.aligned.m8n8.x4.shared.b16 {%0,%1,%2,%3}, [%4];"
                 : "=r"(r[0]), "=r"(r[1]), "=r"(r[2]), "=r"(r[3]) : "r"(addr));
}
__device__ __forceinline__ void lds4t(uint32_t* r, uint32_t addr) {
    asm volatile("ldmatrix.sync.aligned.m8n8.x4.trans.shared.b16 {%0,%1,%2,%3}, [%4];"
                 : "=r"(r[0]), "=r"(r[1]), "=r"(r[2]), "=r"(r[3]) : "r"(addr));
}
__device__ __forceinline__ void mma16816(float* d, const uint32_t* a, const uint32_t* b) {
    asm volatile(
        "mma.sync.aligned.m16n8k16.row.col.f32.bf16.bf16.f32 "
        "{%0,%1,%2,%3}, {%4,%5,%6,%7}, {%8,%9}, {%0,%1,%2,%3};"
        : "+f"(d[0]), "+f"(d[1]), "+f"(d[2]), "+f"(d[3])
        : "r"(a[0]), "r"(a[1]), "r"(a[2]), "r"(a[3]), "r"(b[0]), "r"(b[1]));
}
#define CP_ASYNC16(dst, src) \
    asm volatile("cp.async.cg.shared.global [%0], [%1], 16;" :: "r"(dst), "l"(src))
#define CP_COMMIT() asm volatile("cp.async.commit_group;" ::: "memory")
#define CP_WAIT0()  asm volatile("cp.async.wait_group 0;" ::: "memory")
#define CP_WAIT1()  asm volatile("cp.async.wait_group 1;" ::: "memory")

__device__ __forceinline__ void split2(float a, float b, uint32_t& hi, uint32_t& lo) {
    __nv_bfloat16 ah = __float2bfloat16(a);
    __nv_bfloat16 bh = __float2bfloat16(b);
    __nv_bfloat16 al = __float2bfloat16(a - __bfloat162float(ah));
    __nv_bfloat16 bl = __float2bfloat16(b - __bfloat162float(bh));
    hi = (uint32_t)__bfloat16_as_ushort(ah) | ((uint32_t)__bfloat16_as_ushort(bh) << 16);
    lo = (uint32_t)__bfloat16_as_ushort(al) | ((uint32_t)__bfloat16_as_ushort(bl) << 16);
}

// FMA-pipe exp (avoids MUFU bottleneck): exp(x), x <= 0. rel err ~2.4e-6.
__device__ __forceinline__ float expf_fast(float x) {
    float z = fmaxf(x * 1.442695040888963f, -126.0f);
    float r = z + 12582912.0f;                       // round-to-nearest-int magic
    int   n = __float_as_int(r) - 0x4B400000;
    float f = z - (r - 12582912.0f);                 // f in [-0.5, 0.5]
    float gg = f * 0.6931471805599453f;
    float p = fmaf(gg, 0.008333333f, 0.041666667f);
    p = fmaf(gg, p, 0.166666667f);
    p = fmaf(gg, p, 0.5f);
    p = fmaf(gg, p, 1.0f);
    p = fmaf(gg, p, 1.0f);
    return __int_as_float((n + 127) << 23) * p;
}

// ---------------------------------------------------------------------------
// Prep kernels: weight hi/lo split; mask -> float
// ---------------------------------------------------------------------------
__global__ __launch_bounds__(256) void wsplit_kernel(
    const float* __restrict__ Wq, const float* __restrict__ Wk,
    const float* __restrict__ Wv, const float* __restrict__ Wo)
{
    const int g = blockIdx.y;
    const float* W = (g == 0) ? Wq : (g == 1) ? Wk : (g == 2) ? Wv : Wo;
    const int idx = blockIdx.x * 256 + threadIdx.x;
    float4 x = ((const float4*)W)[idx];
    uint32_t h0, l0, h1, l1;
    split2(x.x, x.y, h0, l0);
    split2(x.z, x.w, h1, l1);
    uint2* WH = (uint2*)(g_wh + (size_t)g * HID_ * HDK_);
    uint2* WL = (uint2*)(g_wl + (size_t)g * HID_ * HDK_);
    WH[idx] = make_uint2(h0, h1);
    WL[idx] = make_uint2(l0, l1);
}

__global__ void maskprep_kernel(const int* __restrict__ mask) {
    int i = blockIdx.x * 256 + threadIdx.x;
    if (i < B_ * S_) g_maskf[i] = (mask[i] != 0) ? 1.0f : 0.0f;
}

// ---------------------------------------------------------------------------
// bf16x3 HMMA GEMM core (unchanged from R3). CTA 128x128, 8 warps.
// ---------------------------------------------------------------------------
#define A_PAD 40
#define B_PAD 136
#define OFF_AL 10240
#define OFF_BH 20480
#define OFF_BL 29184
#define STAGE_ 37888
#define GSM_BYTES (2 * STAGE_)

__device__ __forceinline__ void ldgA(const float* __restrict__ X, int m0, int k0,
                                     int tid, float4* pa) {
    const int r = tid >> 1, cb = (tid & 1) * 16;
    const float* src = X + (size_t)(m0 + r) * HID_ + k0 + cb;
    pa[0] = *(const float4*)(src);
    pa[1] = *(const float4*)(src + 4);
    pa[2] = *(const float4*)(src + 8);
    pa[3] = *(const float4*)(src + 12);
}
__device__ __forceinline__ void stsA(char* aHp, char* aLp, int tid, const float4* pa) {
    const int r = tid >> 1, cb = (tid & 1) * 16;
    uint32_t hi[8], lo[8];
    #pragma unroll
    for (int i = 0; i < 4; i++) {
        split2(pa[i].x, pa[i].y, hi[2*i],   lo[2*i]);
        split2(pa[i].z, pa[i].w, hi[2*i+1], lo[2*i+1]);
    }
    const uint32_t off = (uint32_t)(r * A_PAD + cb) * 2;
    *(uint4*)(aHp + off)      = make_uint4(hi[0], hi[1], hi[2], hi[3]);
    *(uint4*)(aHp + off + 16) = make_uint4(hi[4], hi[5], hi[6], hi[7]);
    *(uint4*)(aLp + off)      = make_uint4(lo[0], lo[1], lo[2], lo[3]);
    *(uint4*)(aLp + off + 16) = make_uint4(lo[4], lo[5], lo[6], lo[7]);
}
__device__ __forceinline__ void cpB(uint32_t bH, uint32_t bL,
                                    const __nv_bfloat16* __restrict__ WHp,
                                    const __nv_bfloat16* __restrict__ WLp,
                                    int n0, int k0, int tid) {
    #pragma unroll
    for (int i = 0; i < 2; i++) {
        const int q = tid + i * 256;
        const int row = q >> 4, c8 = (q & 15) * 8;
        const size_t g = (size_t)(k0 + row) * HDK_ + n0 + c8;
        const uint32_t d = (uint32_t)(row * B_PAD + c8) * 2;
        CP_ASYNC16(bH + d, WHp + g);
        CP_ASYNC16(bL + d, WLp + g);
    }
}

__device__ __forceinline__ void gemm_main(
    const float* __restrict__ X,
    const __nv_bfloat16* __restrict__ WH, const __nv_bfloat16* __restrict__ WL,
    int m0, int n0, char* smc, uint32_t smb, float acc[2][8][4])
{
    const int tid  = threadIdx.x;
    const int lane = tid & 31;
    const int warp = tid >> 5;
    const int m0w  = (warp >> 1) * 32;
    const int n0w  = (warp & 1) * 64;
    const int arow = m0w + (lane & 15);
    const int acol = (lane >> 4) * 8;
    const int brow = lane & 15;
    const int bcol = n0w + (lane >> 4) * 8;

    float4 pa[4];
    ldgA(X, m0, 0, tid, pa);
    cpB(smb + OFF_BH, smb + OFF_BL, WH, WL, n0, 0, tid);
    CP_COMMIT();
    stsA(smc, smc + OFF_AL, tid, pa);
    CP_WAIT0();
    __syncthreads();

    for (int c = 0; c < 32; ++c) {
        const int s = c & 1;
        const uint32_t sb = smb + s * STAGE_;
        char* scn = smc + (s ^ 1) * STAGE_;

        if (c + 1 < 32) {
            ldgA(X, m0, (c + 1) * 32, tid, pa);
            cpB(smb + (s ^ 1) * STAGE_ + OFF_BH, smb + (s ^ 1) * STAGE_ + OFF_BL,
                WH, WL, n0, (c + 1) * 32, tid);
            CP_COMMIT();
        }

        #pragma unroll
        for (int ks = 0; ks < 2; ++ks) {
            uint32_t ah[2][4], al[2][4];
            #pragma unroll
            for (int mf = 0; mf < 2; ++mf) {
                const uint32_t aoff = (uint32_t)((arow + mf * 16) * A_PAD + ks * 16 + acol) * 2;
                lds4(ah[mf], sb + aoff);
                lds4(al[mf], sb + OFF_AL + aoff);
            }
            #pragma unroll
            for (int np = 0; np < 4; ++np) {
                const uint32_t boff = (uint32_t)((ks * 16 + brow) * B_PAD + bcol + np * 16) * 2;
                uint32_t bh[4], bl[4];
                lds4t(bh, sb + OFF_BH + boff);
                lds4t(bl, sb + OFF_BL + boff);
                #pragma unroll
                for (int mf = 0; mf < 2; ++mf) {
                    mma16816(acc[mf][2*np],   ah[mf], bh);
                    mma16816(acc[mf][2*np+1], ah[mf], bh + 2);
                    mma16816(acc[mf][2*np],   ah[mf], bl);
                    mma16816(acc[mf][2*np+1], ah[mf], bl + 2);
                    mma16816(acc[mf][2*np],   al[mf], bh);
                    mma16816(acc[mf][2*np+1], al[mf], bh + 2);
                }
            }
        }
        if (c + 1 < 32) stsA(scn, scn + OFF_AL, tid, pa);
        CP_WAIT0();
        __syncthreads();
    }
}

// ---------------------------------------------------------------------------
// Projection GEMMs -> head-major bf16 hi/lo outputs (Q pre-scaled)
// ---------------------------------------------------------------------------
__global__ __launch_bounds__(256, 1) void proj_tc_kernel(
    const float* __restrict__ q, const float* __restrict__ k, const float* __restrict__ v,
    const float* __restrict__ bq, const float* __restrict__ bk, const float* __restrict__ bv)
{
    extern __shared__ char smc[];
    const uint32_t smb = smem_u32(smc);

    const int z = blockIdx.z;
    const float* X    = (z == 0) ? q  : (z == 1) ? k  : v;
    const float* bias = (z == 0) ? bq : (z == 1) ? bk : bv;
    const __nv_bfloat16* WH = g_wh + (size_t)z * HID_ * HDK_;
    const __nv_bfloat16* WL = g_wl + (size_t)z * HID_ * HDK_;
    __nv_bfloat16* Yh = (z == 0) ? g_qhi : (z == 1) ? g_khi : g_vhi;
    __nv_bfloat16* Yl = (z == 0) ? g_qlo : (z == 1) ? g_klo : g_vlo;
    const float osc = (z == 0) ? SCALE_ : 1.0f;

    const int m0 = blockIdx.y * 128, n0 = blockIdx.x * 128;
    float acc[2][8][4] = {};
    gemm_main(X, WH, WL, m0, n0, smc, smb, acc);

    const int lane = threadIdx.x & 31, warp = threadIdx.x >> 5;
    const int m0w = (warp >> 1) * 32, n0w = (warp & 1) * 64;
    #pragma unroll
    for (int mf = 0; mf < 2; ++mf) {
        #pragma unroll
        for (int nf = 0; nf < 8; ++nf) {
            const int mr = m0 + m0w + mf * 16 + (lane >> 2);
            const int nn = n0 + n0w + nf * 8 + (lane & 3) * 2;
            const int hh = nn >> 6, dk = nn & 63;
            const float b0 = bias[nn], b1 = bias[nn + 1];
            #pragma unroll
            for (int rr = 0; rr < 2; ++rr) {
                const int m = mr + rr * 8;
                const int bb = m >> 11, ss = m & 2047;
                float v0 = (acc[mf][nf][2*rr]     + b0) * osc;
                float v1 = (acc[mf][nf][2*rr + 1] + b1) * osc;
                uint32_t hi, lo;
                split2(v0, v1, hi, lo);
                size_t idx = (((size_t)bb * H_ + hh) * S_ + ss) * DK_ + dk;
                *(uint32_t*)&Yh[idx] = hi;
                *(uint32_t*)&Yl[idx] = lo;
            }
        }
    }
}

// ---------------------------------------------------------------------------
// HMMA flash attention. CTA = 128 q-rows of one (b,h), 8 warps x m16.
// S-tiles of 64 keys, K/V hi/lo via 2-stage cp.async; bias/mask via LDG.
// ---------------------------------------------------------------------------
#define QH_OFF  0
#define QL_OFF  18432
#define KV_OFF  36864
#define KV_ST   36864
#define ATTN_SMEM (KV_OFF + 2 * KV_ST)   // 110592

__device__ __forceinline__ void cp_kv(uint32_t dstbase,
    const __nv_bfloat16* __restrict__ KHg, const __nv_bfloat16* __restrict__ KLg,
    const __nv_bfloat16* __restrict__ VHg, const __nv_bfloat16* __restrict__ VLg,
    int k0, int tid)
{
    #pragma unroll
    for (int i = 0; i < 8; i++) {
        int idx = tid + i * 256;
        int mat = idx >> 9, rem = idx & 511;
        int row = rem >> 3, c8 = (rem & 7) * 8;
        const __nv_bfloat16* src =
            ((mat == 0) ? KHg : (mat == 1) ? KLg : (mat == 2) ? VHg : VLg)
            + (size_t)(k0 + row) * DK_ + c8;
        uint32_t dst = dstbase + mat * 9216 + (uint32_t)(row * 72 + c8) * 2;
        CP_ASYNC16(dst, src);
    }
}

__global__ __launch_bounds__(256, 1) void attn_tc_kernel(
    const float* __restrict__ attn_bias, const int* __restrict__ mask)
{
    extern __shared__ char sm[];
    const uint32_t smb = smem_u32(sm);
    const int tid = threadIdx.x;
    const int lane = tid & 31, warp = tid >> 5;
    const int g = lane >> 2, tig = lane & 3;
    const int q0 = blockIdx.x * 128;
    const int h = blockIdx.y, b = blockIdx.z;

    const size_t hb = ((size_t)b * H_ + h) * S_ * DK_;
    const __nv_bfloat16* QHg = g_qhi + hb + (size_t)q0 * DK_;
    const __nv_bfloat16* QLg = g_qlo + hb + (size_t)q0 * DK_;
    const __nv_bfloat16* KHg = g_khi + hb;
    const __nv_bfloat16* KLg = g_klo + hb;
    const __nv_bfloat16* VHg = g_vhi + hb;
    const __nv_bfloat16* VLg = g_vlo + hb;

    // Load Q hi/lo into padded smem
    #pragma unroll
    for (int i = 0; i < 4; i++) {
        int idx = tid + i * 256;               // 1024 chunks of 16B
        int row = idx >> 3, c8 = (idx & 7) * 8;
        uint32_t d = (uint32_t)(row * 72 + c8) * 2;
        *(uint4*)(sm + QH_OFF + d) = *(const uint4*)(QHg + (size_t)row * DK_ + c8);
        *(uint4*)(sm + QL_OFF + d) = *(const uint4*)(QLg + (size_t)row * DK_ + c8);
    }

    // Prologue: tile 0 -> stage 0
    cp_kv(smb + KV_OFF, KHg, KLg, VHg, VLg, 0, tid);
    CP_COMMIT();

    const int qr0 = q0 + warp * 16 + g;
    const float* biasrow = attn_bias + (((size_t)b * H_ + h) * S_ + qr0) * S_;
    const float* mfb = g_maskf + b * S_;

    float oa[8][4] = {};
    float mrow0 = -INFINITY, mrow8 = -INFINITY;
    float lrow0 = 0.f, lrow8 = 0.f;

    const uint32_t qaddr_base = smb + QH_OFF +
        (uint32_t)((warp * 16 + (lane & 15)) * 72 + (lane >> 4) * 8) * 2;
    const uint32_t kaddr_base = (uint32_t)(((lane & 7) + ((lane & 16) >> 1)) * 72
                                           + (lane & 8)) * 2;
    const uint32_t vaddr_base = (uint32_t)((lane & 15) * 72 + (lane >> 4) * 8) * 2;

    for (int t = 0; t < 32; ++t) {
        const int k0 = t * 64;
        const int s = t & 1;
        const uint32_t sb = smb + KV_OFF + s * KV_ST;

        if (t + 1 < 32) {
            cp_kv(smb + KV_OFF + (s ^ 1) * KV_ST, KHg, KLg, VHg, VLg, (t + 1) * 64, tid);
            CP_COMMIT();
        }

        // bias/mask prefetch into registers (each element read once)
        float2 b0r[8], b1r[8], mr[8];
        #pragma unroll
        for (int nf = 0; nf < 8; nf++) {
            int c = k0 + 8 * nf + 2 * tig;
            b0r[nf] = *(const float2*)&biasrow[c];
            b1r[nf] = *(const float2*)&biasrow[c + 8 * S_];
            mr[nf]  = *(const float2*)&mfb[c];
        }

        if (t + 1 < 32) { CP_WAIT1(); } else { CP_WAIT0(); }
        __syncthreads();

        // S = Q K^T  (bf16x3)
        float sa[8][4];
        #pragma unroll
        for (int i = 0; i < 8; i++)
            #pragma unroll
            for (int j = 0; j < 4; j++) sa[i][j] = 0.f;

        #pragma unroll
        for (int ks = 0; ks < 4; ks++) {
            uint32_t qh[4], ql[4];
            uint32_t qaddr = qaddr_base + (uint32_t)(ks * 16) * 2;
            lds4(qh, qaddr);
            lds4(ql, qaddr + QL_OFF);
            #pragma unroll
            for (int nf = 0; nf < 4; nf++) {
                uint32_t kaddr = sb + kaddr_base
                               + (uint32_t)(nf * 16 * 72 + ks * 16) * 2;
                uint32_t kh[4], kl[4];
                lds4(kh, kaddr);
                lds4(kl, kaddr + 9216);
                mma16816(sa[2*nf],   qh, kh);
                mma16816(sa[2*nf+1], qh, kh + 2);
                mma16816(sa[2*nf],   qh, kl);
                mma16816(sa[2*nf+1], qh, kl + 2);
                mma16816(sa[2*nf],   ql, kh);
                mma16816(sa[2*nf+1], ql, kh + 2);
            }
        }

        // mask-select + bias (NOT additive NEG: keeps fp32 score precision)
        #pragma unroll
        for (int nf = 0; nf < 8; nf++) {
            sa[nf][0] = ((mr[nf].x != 0.f) ? sa[nf][0] : NEG_) + b0r[nf].x;
            sa[nf][1] = ((mr[nf].y != 0.f) ? sa[nf][1] : NEG_) + b0r[nf].y;
            sa[nf][2] = ((mr[nf].x != 0.f) ? sa[nf][2] : NEG_) + b1r[nf].x;
            sa[nf][3] = ((mr[nf].y != 0.f) ? sa[nf][3] : NEG_) + b1r[nf].y;
        }

        // online softmax (FMA-pipe exp)
        float mx0 = -INFINITY, mx8 = -INFINITY;
        #pragma unroll
        for (int nf = 0; nf < 8; nf++) {
            mx0 = fmaxf(mx0, fmaxf(sa[nf][0], sa[nf][1]));
            mx8 = fmaxf(mx8, fmaxf(sa[nf][2], sa[nf][3]));
        }
        mx0 = fmaxf(mx0, __shfl_xor_sync(0xffffffffu, mx0, 1));
        mx0 = fmaxf(mx0, __shfl_xor_sync(0xffffffffu, mx0, 2));
        mx8 = fmaxf(mx8, __shfl_xor_sync(0xffffffffu, mx8, 1));
        mx8 = fmaxf(mx8, __shfl_xor_sync(0xffffffffu, mx8, 2));
        float mn0 = fmaxf(mrow0, mx0), mn8 = fmaxf(mrow8, mx8);
        float fac0 = expf_fast(mrow0 - mn0), fac8 = expf_fast(mrow8 - mn8);
        mrow0 = mn0; mrow8 = mn8;

        float ps0 = 0.f, ps8 = 0.f;
        #pragma unroll
        for (int nf = 0; nf < 8; nf++) {
            sa[nf][0] = expf_fast(sa[nf][0] - mn0);
            sa[nf][1] = expf_fast(sa[nf][1] - mn0);
            sa[nf][2] = expf_fast(sa[nf][2] - mn8);
            sa[nf][3] = expf_fast(sa[nf][3] - mn8);
            ps0 += sa[nf][0] + sa[nf][1];
            ps8 += sa[nf][2] + sa[nf][3];
        }
        ps0 += __shfl_xor_sync(0xffffffffu, ps0, 1);
        ps0 += __shfl_xor_sync(0xffffffffu, ps0, 2);
        ps8 += __shfl_xor_sync(0xffffffffu, ps8, 1);
        ps8 += __shfl_xor_sync(0xffffffffu, ps8, 2);
        lrow0 = lrow0 * fac0 + ps0;
        lrow8 = lrow8 * fac8 + ps8;
        #pragma unroll
        for (int nf = 0; nf < 8; nf++) {
            oa[nf][0] *= fac0; oa[nf][1] *= fac0;
            oa[nf][2] *= fac8; oa[nf][3] *= fac8;
        }

        // O += P V  (P split hi/lo in-register; bf16x3)
        #pragma unroll
        for (int ks = 0; ks < 4; ks++) {
            uint32_t ph[4], pl[4];
            split2(sa[2*ks][0],   sa[2*ks][1],   ph[0], pl[0]);
            split2(sa[2*ks][2],   sa[2*ks][3],   ph[1], pl[1]);
            split2(sa[2*ks+1][0], sa[2*ks+1][1], ph[2], pl[2]);
            split2(sa[2*ks+1][2], sa[2*ks+1][3], ph[3], pl[3]);
            #pragma unroll
            for (int nf = 0; nf < 4; nf++) {
                uint32_t vaddr = sb + 18432 + vaddr_base
                               + (uint32_t)(ks * 16 * 72 + nf * 16) * 2;
                uint32_t vh[4], vl[4];
                lds4t(vh, vaddr);
                lds4t(vl, vaddr + 9216);
                mma16816(oa[2*nf],   ph, vh);
                mma16816(oa[2*nf+1], ph, vh + 2);
                mma16816(oa[2*nf],   ph, vl);
                mma16816(oa[2*nf+1], ph, vl + 2);
                mma16816(oa[2*nf],   pl, vh);
                mma16816(oa[2*nf+1], pl, vh + 2);
            }
        }
        __syncthreads();
    }

    // epilogue: normalize, q-mask, write token-major xh
    float qm0 = (mask[b * S_ + qr0]     != 0) ? 1.f : 0.f;
    float qm8 = (mask[b * S_ + qr0 + 8] != 0) ? 1.f : 0.f;
    float inv0 = qm0 / lrow0, inv8 = qm8 / lrow8;
    #pragma unroll
    for (int nf = 0; nf < 8; nf++) {
        int col = h * DK_ + 8 * nf + 2 * tig;
        *(float2*)&g_xh[(size_t)(b * S_ + qr0) * HDK_ + col] =
            make_float2(oa[nf][0] * inv0, oa[nf][1] * inv0);
        *(float2*)&g_xh[(size_t)(b * S_ + qr0 + 8) * HDK_ + col] =
            make_float2(oa[nf][2] * inv8, oa[nf][3] * inv8);
    }
}

// ---------------------------------------------------------------------------
// Output GEMM: out = xh @ Wo + bo (unchanged)
// ---------------------------------------------------------------------------
__global__ __launch_bounds__(256, 1) void out_tc_kernel(
    const float* __restrict__ bo, float* __restrict__ out)
{
    extern __shared__ char smc[];
    const uint32_t smb = smem_u32(smc);

    const __nv_bfloat16* WH = g_wh + (size_t)3 * HID_ * HDK_;
    const __nv_bfloat16* WL = g_wl + (size_t)3 * HID_ * HDK_;

    const int m0 = blockIdx.y * 128, n0 = blockIdx.x * 128;
    float acc[2][8][4] = {};
    gemm_main(g_xh, WH, WL, m0, n0, smc, smb, acc);

    const int lane = threadIdx.x & 31, warp = threadIdx.x >> 5;
    const int m0w = (warp >> 1) * 32, n0w = (warp & 1) * 64;
    #pragma unroll
    for (int mf = 0; mf < 2; ++mf) {
        #pragma unroll
        for (int nf = 0; nf < 8; ++nf) {
            const int mr = m0 + m0w + mf * 16 + (lane >> 2);
            const int nn = n0 + n0w + nf * 8 + (lane & 3) * 2;
            const float b0 = bo[nn], b1 = bo[nn + 1];
            *(float2*)&out[(size_t)mr * HDK_ + nn] =
                make_float2(acc[mf][nf][0] + b0, acc[mf][nf][1] + b1);
            *(float2*)&out[(size_t)(mr + 8) * HDK_ + nn] =
                make_float2(acc[mf][nf][2] + b0, acc[mf][nf][3] + b1);
        }
    }
}

// ---------------------------------------------------------------------------
extern "C" void kernel_launch(void* const* d_in, const int* in_sizes, int n_in,
                              void* d_out, int out_size)
{
    const float* q         = (const float*)d_in[0];
    const float* k         = (const float*)d_in[1];
    const float* v         = (const float*)d_in[2];
    const float* attn_bias = (const float*)d_in[3];
    const int*   mask      = (const int*)  d_in[4];
    const float* Wq        = (const float*)d_in[5];
    const float* bq        = (const float*)d_in[6];
    const float* Wk        = (const float*)d_in[7];
    const float* bk        = (const float*)d_in[8];
    const float* Wv        = (const float*)d_in[9];
    const float* bv        = (const float*)d_in[10];
    const float* Wo        = (const float*)d_in[11];
    const float* bo        = (const float*)d_in[12];
    float* out = (float*)d_out;

    static int configured = 0;
    if (!configured) {
        cudaFuncSetAttribute(proj_tc_kernel, cudaFuncAttributeMaxDynamicSharedMemorySize, GSM_BYTES);
        cudaFuncSetAttribute(out_tc_kernel,  cudaFuncAttributeMaxDynamicSharedMemorySize, GSM_BYTES);
        cudaFuncSetAttribute(attn_tc_kernel, cudaFuncAttributeMaxDynamicSharedMemorySize, ATTN_SMEM);
        configured = 1;
    }

    wsplit_kernel<<<dim3(HID_ * HDK_ / 4 / 256, 4), 256>>>(Wq, Wk, Wv, Wo);
    maskprep_kernel<<<(B_ * S_ + 255) / 256, 256>>>(mask);

    proj_tc_kernel<<<dim3(HDK_ / 128, M_ / 128, 3), 256, GSM_BYTES>>>(q, k, v, bq, bk, bv);

    attn_tc_kernel<<<dim3(S_ / 128, H_, B_), 256, ATTN_SMEM>>>(attn_bias, mask);

    out_tc_kernel<<<dim3(HDK_ / 128, M_ / 128), 256, GSM_BYTES>>>(bo, out);
}

// round 5
// speedup vs baseline: 2.2503x; 1.1368x over previous
#include <cuda_runtime.h>
#include <cuda_bf16.h>
#include <math.h>
#include <stdint.h>

#define B_    2
#define S_    2048
#define HID_  1024
#define H_    16
#define DK_   64
#define HDK_  1024
#define M_    4096
#define SCALE_ 0.125f
#define NEG_  -1000000000.0f

// Scratch (allocation-free device globals)
__device__ __nv_bfloat16 g_qhi[B_*H_*S_*DK_], g_qlo[B_*H_*S_*DK_];
__device__ __nv_bfloat16 g_khi[B_*H_*S_*DK_], g_klo[B_*H_*S_*DK_];
__device__ __nv_bfloat16 g_vhi[B_*H_*S_*DK_], g_vlo[B_*H_*S_*DK_];
__device__ float g_xh[M_*HDK_];                 // attention out, token-major
__device__ float g_maskf[B_*S_];                // mask as float 0/1
__device__ __nv_bfloat16 g_wh[4u*HID_*HDK_];    // W hi, [g][k][n]
__device__ __nv_bfloat16 g_wl[4u*HID_*HDK_];    // W lo

// ---------------------------------------------------------------------------
// sm_80-class PTX helpers (harness targets compute_103: no 'a' features)
// ---------------------------------------------------------------------------
__device__ __forceinline__ uint32_t smem_u32(const void* p) {
    uint32_t a;
    asm("{ .reg .u64 t; cvta.to.shared.u64 t, %1; cvt.u32.u64 %0, t; }"
        : "=r"(a) : "l"(p));
    return a;
}
__device__ __forceinline__ void lds4(uint32_t* r, uint32_t addr) {
    asm volatile("ldmatrix.sync.aligned.m8n8.x4.shared.b16 {%0,%1,%2,%3}, [%4];"
                 : "=r"(r[0]), "=r"(r[1]), "=r"(r[2]), "=r"(r[3]) : "r"(addr));
}
__device__ __forceinline__ void lds4t(uint32_t* r, uint32_t addr) {
    asm volatile("ldmatrix.sync.aligned.m8n8.x4.trans.shared.b16 {%0,%1,%2,%3}, [%4];"
                 : "=r"(r[0]), "=r"(r[1]), "=r"(r[2]), "=r"(r[3]) : "r"(addr));
}
__device__ __forceinline__ void mma16816(float* d, const uint32_t* a, const uint32_t* b) {
    asm volatile(
        "mma.sync.aligned.m16n8k16.row.col.f32.bf16.bf16.f32 "
        "{%0,%1,%2,%3}, {%4,%5,%6,%7}, {%8,%9}, {%0,%1,%2,%3};"
        : "+f"(d[0]), "+f"(d[1]), "+f"(d[2]), "+f"(d[3])
        : "r"(a[0]), "r"(a[1]), "r"(a[2]), "r"(a[3]), "r"(b[0]), "r"(b[1]));
}
#define CP_ASYNC16(dst, src) \
    asm volatile("cp.async.cg.shared.global [%0], [%1], 16;" :: "r"(dst), "l"(src))
#define CP_COMMIT() asm volatile("cp.async.commit_group;" ::: "memory")
#define CP_WAIT0()  asm volatile("cp.async.wait_group 0;" ::: "memory")
#define CP_WAIT1()  asm volatile("cp.async.wait_group 1;" ::: "memory")

__device__ __forceinline__ void split2(float a, float b, uint32_t& hi, uint32_t& lo) {
    __nv_bfloat16 ah = __float2bfloat16(a);
    __nv_bfloat16 bh = __float2bfloat16(b);
    __nv_bfloat16 al = __float2bfloat16(a - __bfloat162float(ah));
    __nv_bfloat16 bl = __float2bfloat16(b - __bfloat162float(bh));
    hi = (uint32_t)__bfloat16_as_ushort(ah) | ((uint32_t)__bfloat16_as_ushort(bh) << 16);
    lo = (uint32_t)__bfloat16_as_ushort(al) | ((uint32_t)__bfloat16_as_ushort(bl) << 16);
}

// FMA-pipe exp (avoids MUFU bottleneck): exp(x), x <= 0. rel err ~2.4e-6.
__device__ __forceinline__ float expf_fast(float x) {
    float z = fmaxf(x * 1.442695040888963f, -126.0f);
    float r = z + 12582912.0f;
    int   n = __float_as_int(r) - 0x4B400000;
    float f = z - (r - 12582912.0f);
    float gg = f * 0.6931471805599453f;
    float p = fmaf(gg, 0.008333333f, 0.041666667f);
    p = fmaf(gg, p, 0.166666667f);
    p = fmaf(gg, p, 0.5f);
    p = fmaf(gg, p, 1.0f);
    p = fmaf(gg, p, 1.0f);
    return __int_as_float((n + 127) << 23) * p;
}

// ---------------------------------------------------------------------------
// Prep kernels
// ---------------------------------------------------------------------------
__global__ __launch_bounds__(256) void wsplit_kernel(
    const float* __restrict__ Wq, const float* __restrict__ Wk,
    const float* __restrict__ Wv, const float* __restrict__ Wo)
{
    const int g = blockIdx.y;
    const float* W = (g == 0) ? Wq : (g == 1) ? Wk : (g == 2) ? Wv : Wo;
    const int idx = blockIdx.x * 256 + threadIdx.x;
    float4 x = ((const float4*)W)[idx];
    uint32_t h0, l0, h1, l1;
    split2(x.x, x.y, h0, l0);
    split2(x.z, x.w, h1, l1);
    uint2* WH = (uint2*)(g_wh + (size_t)g * HID_ * HDK_);
    uint2* WL = (uint2*)(g_wl + (size_t)g * HID_ * HDK_);
    WH[idx] = make_uint2(h0, h1);
    WL[idx] = make_uint2(l0, l1);
}

__global__ void maskprep_kernel(const int* __restrict__ mask) {
    int i = blockIdx.x * 256 + threadIdx.x;
    if (i < B_ * S_) g_maskf[i] = (mask[i] != 0) ? 1.0f : 0.0f;
}

// ---------------------------------------------------------------------------
// bf16x3 HMMA GEMM core. CTA 128x128, 8 warps, K-chunk 16, 2-stage smem,
// 2 CTAs/SM. Stage: AH[128][24] 6144 | AL 6144 | BH[16][136] 4352 | BL 4352.
// ---------------------------------------------------------------------------
#define A_PAD 24
#define OFF_AL 6144
#define OFF_BH 12288
#define OFF_BL 16640
#define STAGE_ 20992
#define GSM_BYTES (2 * STAGE_)

__device__ __forceinline__ void ldgA(const float* __restrict__ X, int m0, int k0,
                                     int tid, float4* pa) {
    const int r = tid >> 1, c8 = (tid & 1) * 8;
    const float* src = X + (size_t)(m0 + r) * HID_ + k0 + c8;
    pa[0] = *(const float4*)(src);
    pa[1] = *(const float4*)(src + 4);
}
__device__ __forceinline__ void stsA(char* aHp, char* aLp, int tid, const float4* pa) {
    const int r = tid >> 1, c8 = (tid & 1) * 8;
    uint32_t hi[4], lo[4];
    split2(pa[0].x, pa[0].y, hi[0], lo[0]);
    split2(pa[0].z, pa[0].w, hi[1], lo[1]);
    split2(pa[1].x, pa[1].y, hi[2], lo[2]);
    split2(pa[1].z, pa[1].w, hi[3], lo[3]);
    const uint32_t off = (uint32_t)(r * A_PAD + c8) * 2;
    *(uint4*)(aHp + off) = make_uint4(hi[0], hi[1], hi[2], hi[3]);
    *(uint4*)(aLp + off) = make_uint4(lo[0], lo[1], lo[2], lo[3]);
}
__device__ __forceinline__ void cpB(uint32_t bbase,
                                    const __nv_bfloat16* __restrict__ WHp,
                                    const __nv_bfloat16* __restrict__ WLp,
                                    int n0, int k0, int tid) {
    #pragma unroll
    for (int i = 0; i < 2; i++) {
        const int idx = tid + i * 256;            // 512 chunks total (2 mats)
        const int mat = idx >> 8, rem = idx & 255;
        const int row = rem >> 4, c8 = (rem & 15) * 8;
        const size_t g = (size_t)(k0 + row) * HDK_ + n0 + c8;
        const uint32_t d = bbase + mat * 4352 + (uint32_t)(row * 136 + c8) * 2;
        CP_ASYNC16(d, (mat == 0 ? WHp : WLp) + g);
    }
}

__device__ __forceinline__ void gemm_main(
    const float* __restrict__ X,
    const __nv_bfloat16* __restrict__ WH, const __nv_bfloat16* __restrict__ WL,
    int m0, int n0, char* smc, uint32_t smb, float acc[2][8][4])
{
    const int tid  = threadIdx.x;
    const int lane = tid & 31;
    const int warp = tid >> 5;
    const int m0w  = (warp >> 1) * 32;
    const int n0w  = (warp & 1) * 64;
    const int arow = m0w + (lane & 15);
    const int acol = (lane >> 4) * 8;
    const int brow = lane & 15;
    const int bcol = n0w + (lane >> 4) * 8;

    float4 pa[2];
    ldgA(X, m0, 0, tid, pa);
    cpB(smb + OFF_BH, WH, WL, n0, 0, tid);
    CP_COMMIT();
    stsA(smc, smc + OFF_AL, tid, pa);
    CP_WAIT0();
    __syncthreads();

    for (int c = 0; c < 64; ++c) {
        const int s = c & 1;
        const uint32_t sb = smb + s * STAGE_;
        char* scn = smc + (s ^ 1) * STAGE_;

        if (c + 1 < 64) {
            ldgA(X, m0, (c + 1) * 16, tid, pa);
            cpB(smb + (s ^ 1) * STAGE_ + OFF_BH, WH, WL, n0, (c + 1) * 16, tid);
            CP_COMMIT();
        }

        uint32_t ah[2][4], al[2][4];
        #pragma unroll
        for (int mf = 0; mf < 2; ++mf) {
            const uint32_t aoff = (uint32_t)((arow + mf * 16) * A_PAD + acol) * 2;
            lds4(ah[mf], sb + aoff);
            lds4(al[mf], sb + OFF_AL + aoff);
        }
        #pragma unroll
        for (int np = 0; np < 4; ++np) {
            const uint32_t boff = (uint32_t)(brow * 136 + bcol + np * 16) * 2;
            uint32_t bh[4], bl[4];
            lds4t(bh, sb + OFF_BH + boff);
            lds4t(bl, sb + OFF_BL + boff);
            #pragma unroll
            for (int mf = 0; mf < 2; ++mf) {
                mma16816(acc[mf][2*np],   ah[mf], bh);
                mma16816(acc[mf][2*np+1], ah[mf], bh + 2);
                mma16816(acc[mf][2*np],   ah[mf], bl);
                mma16816(acc[mf][2*np+1], ah[mf], bl + 2);
                mma16816(acc[mf][2*np],   al[mf], bh);
                mma16816(acc[mf][2*np+1], al[mf], bh + 2);
            }
        }

        if (c + 1 < 64) stsA(scn, scn + OFF_AL, tid, pa);
        CP_WAIT0();
        __syncthreads();
    }
}

// ---------------------------------------------------------------------------
// Projection GEMMs -> head-major bf16 hi/lo outputs (Q pre-scaled)
// ---------------------------------------------------------------------------
__global__ __launch_bounds__(256, 2) void proj_tc_kernel(
    const float* __restrict__ q, const float* __restrict__ k, const float* __restrict__ v,
    const float* __restrict__ bq, const float* __restrict__ bk, const float* __restrict__ bv)
{
    extern __shared__ char smc[];
    const uint32_t smb = smem_u32(smc);

    const int z = blockIdx.z;
    const float* X    = (z == 0) ? q  : (z == 1) ? k  : v;
    const float* bias = (z == 0) ? bq : (z == 1) ? bk : bv;
    const __nv_bfloat16* WH = g_wh + (size_t)z * HID_ * HDK_;
    const __nv_bfloat16* WL = g_wl + (size_t)z * HID_ * HDK_;
    __nv_bfloat16* Yh = (z == 0) ? g_qhi : (z == 1) ? g_khi : g_vhi;
    __nv_bfloat16* Yl = (z == 0) ? g_qlo : (z == 1) ? g_klo : g_vlo;
    const float osc = (z == 0) ? SCALE_ : 1.0f;

    const int m0 = blockIdx.y * 128, n0 = blockIdx.x * 128;
    float acc[2][8][4] = {};
    gemm_main(X, WH, WL, m0, n0, smc, smb, acc);

    const int lane = threadIdx.x & 31, warp = threadIdx.x >> 5;
    const int m0w = (warp >> 1) * 32, n0w = (warp & 1) * 64;
    #pragma unroll
    for (int mf = 0; mf < 2; ++mf) {
        #pragma unroll
        for (int nf = 0; nf < 8; ++nf) {
            const int mr = m0 + m0w + mf * 16 + (lane >> 2);
            const int nn = n0 + n0w + nf * 8 + (lane & 3) * 2;
            const int hh = nn >> 6, dk = nn & 63;
            const float b0 = bias[nn], b1 = bias[nn + 1];
            #pragma unroll
            for (int rr = 0; rr < 2; ++rr) {
                const int m = mr + rr * 8;
                const int bb = m >> 11, ss = m & 2047;
                float v0 = (acc[mf][nf][2*rr]     + b0) * osc;
                float v1 = (acc[mf][nf][2*rr + 1] + b1) * osc;
                uint32_t hi, lo;
                split2(v0, v1, hi, lo);
                size_t idx = (((size_t)bb * H_ + hh) * S_ + ss) * DK_ + dk;
                *(uint32_t*)&Yh[idx] = hi;
                *(uint32_t*)&Yl[idx] = lo;
            }
        }
    }
}

// ---------------------------------------------------------------------------
// HMMA flash attention. CTA = 64 q-rows of one (b,h), 128 threads (4 warps).
// Q frags in registers; K/V 32-key tiles, 2-stage cp.async; 3 CTAs/SM target.
// Stage: KH[32][72] 4608 | KL 4608 | VH 4608 | VL 4608 = 18432; x2 = 36864.
// ---------------------------------------------------------------------------
#define KV_ST 18432
#define ATTN_SMEM (2 * KV_ST)

__device__ __forceinline__ void cp_kv(uint32_t dstbase,
    const __nv_bfloat16* __restrict__ KHg, const __nv_bfloat16* __restrict__ KLg,
    const __nv_bfloat16* __restrict__ VHg, const __nv_bfloat16* __restrict__ VLg,
    int k0, int tid)
{
    #pragma unroll
    for (int i = 0; i < 8; i++) {
        int idx = tid + i * 128;                 // 1024 chunks (4 mats x 256)
        int mat = idx >> 8, rem = idx & 255;
        int row = rem >> 3, c8 = (rem & 7) * 8;
        const __nv_bfloat16* src =
            ((mat == 0) ? KHg : (mat == 1) ? KLg : (mat == 2) ? VHg : VLg)
            + (size_t)(k0 + row) * DK_ + c8;
        uint32_t dst = dstbase + mat * 4608 + (uint32_t)(row * 72 + c8) * 2;
        CP_ASYNC16(dst, src);
    }
}

__global__ __launch_bounds__(128, 3) void attn_tc_kernel(
    const float* __restrict__ attn_bias, const int* __restrict__ mask)
{
    extern __shared__ char sm[];
    const uint32_t smb = smem_u32(sm);
    const int tid = threadIdx.x;
    const int lane = tid & 31, warp = tid >> 5;
    const int g = lane >> 2, tig = lane & 3;
    const int q0 = blockIdx.x * 64;
    const int h = blockIdx.y, b = blockIdx.z;

    const size_t hb = ((size_t)b * H_ + h) * S_ * DK_;
    const __nv_bfloat16* QHg = g_qhi + hb + (size_t)q0 * DK_;
    const __nv_bfloat16* QLg = g_qlo + hb + (size_t)q0 * DK_;
    const __nv_bfloat16* KHg = g_khi + hb;
    const __nv_bfloat16* KLg = g_klo + hb;
    const __nv_bfloat16* VHg = g_vhi + hb;
    const __nv_bfloat16* VLg = g_vlo + hb;

    // Q fragments -> registers, loaded once (mma A-frag layout)
    uint32_t qh[4][4], ql[4][4];
    {
        const int r0 = warp * 16 + g;
        #pragma unroll
        for (int ks = 0; ks < 4; ks++) {
            const int c = ks * 16 + tig * 2;
            qh[ks][0] = *(const uint32_t*)&QHg[(size_t)r0 * DK_ + c];
            qh[ks][1] = *(const uint32_t*)&QHg[(size_t)(r0 + 8) * DK_ + c];
            qh[ks][2] = *(const uint32_t*)&QHg[(size_t)r0 * DK_ + c + 8];
            qh[ks][3] = *(const uint32_t*)&QHg[(size_t)(r0 + 8) * DK_ + c + 8];
            ql[ks][0] = *(const uint32_t*)&QLg[(size_t)r0 * DK_ + c];
            ql[ks][1] = *(const uint32_t*)&QLg[(size_t)(r0 + 8) * DK_ + c];
            ql[ks][2] = *(const uint32_t*)&QLg[(size_t)r0 * DK_ + c + 8];
            ql[ks][3] = *(const uint32_t*)&QLg[(size_t)(r0 + 8) * DK_ + c + 8];
        }
    }

    // Prologue: tile 0 -> stage 0
    cp_kv(smb, KHg, KLg, VHg, VLg, 0, tid);
    CP_COMMIT();

    const int qr0 = q0 + warp * 16 + g;
    const float* biasrow = attn_bias + (((size_t)b * H_ + h) * S_ + qr0) * S_;
    const float* mfb = g_maskf + b * S_;

    float oa[8][4] = {};
    float mrow0 = -INFINITY, mrow8 = -INFINITY;
    float lrow0 = 0.f, lrow8 = 0.f;

    const uint32_t kbase = (uint32_t)(((lane & 7) + ((lane & 16) >> 1)) * 72
                                      + (lane & 8)) * 2;
    const uint32_t vbase = (uint32_t)((lane & 15) * 72 + (lane >> 4) * 8) * 2;

    for (int t = 0; t < 64; ++t) {
        const int k0 = t * 32;
        const int s = t & 1;
        const uint32_t sb = smb + s * KV_ST;

        if (t + 1 < 64) {
            cp_kv(smb + (s ^ 1) * KV_ST, KHg, KLg, VHg, VLg, (t + 1) * 32, tid);
            CP_COMMIT();
        }

        // bias/mask prefetch (overlaps cp.async + previous compute)
        float2 b0r[4], b1r[4], mr[4];
        #pragma unroll
        for (int nf = 0; nf < 4; nf++) {
            int c = k0 + 8 * nf + 2 * tig;
            b0r[nf] = *(const float2*)&biasrow[c];
            b1r[nf] = *(const float2*)&biasrow[c + 8 * S_];
            mr[nf]  = *(const float2*)&mfb[c];
        }

        if (t + 1 < 64) { CP_WAIT1(); } else { CP_WAIT0(); }
        __syncthreads();

        // S = Q K^T (bf16x3), 32 keys
        float sa[4][4];
        #pragma unroll
        for (int i = 0; i < 4; i++)
            #pragma unroll
            for (int j = 0; j < 4; j++) sa[i][j] = 0.f;

        #pragma unroll
        for (int ks = 0; ks < 4; ks++) {
            #pragma unroll
            for (int nf2 = 0; nf2 < 2; nf2++) {
                uint32_t kaddr = sb + kbase + (uint32_t)(nf2 * 16 * 72 + ks * 16) * 2;
                uint32_t kh[4], kl[4];
                lds4(kh, kaddr);
                lds4(kl, kaddr + 4608);
                mma16816(sa[2*nf2],   qh[ks], kh);
                mma16816(sa[2*nf2+1], qh[ks], kh + 2);
                mma16816(sa[2*nf2],   qh[ks], kl);
                mma16816(sa[2*nf2+1], qh[ks], kl + 2);
                mma16816(sa[2*nf2],   ql[ks], kh);
                mma16816(sa[2*nf2+1], ql[ks], kh + 2);
            }
        }

        // mask-select + bias
        #pragma unroll
        for (int nf = 0; nf < 4; nf++) {
            sa[nf][0] = ((mr[nf].x != 0.f) ? sa[nf][0] : NEG_) + b0r[nf].x;
            sa[nf][1] = ((mr[nf].y != 0.f) ? sa[nf][1] : NEG_) + b0r[nf].y;
            sa[nf][2] = ((mr[nf].x != 0.f) ? sa[nf][2] : NEG_) + b1r[nf].x;
            sa[nf][3] = ((mr[nf].y != 0.f) ? sa[nf][3] : NEG_) + b1r[nf].y;
        }

        // online softmax
        float mx0 = -INFINITY, mx8 = -INFINITY;
        #pragma unroll
        for (int nf = 0; nf < 4; nf++) {
            mx0 = fmaxf(mx0, fmaxf(sa[nf][0], sa[nf][1]));
            mx8 = fmaxf(mx8, fmaxf(sa[nf][2], sa[nf][3]));
        }
        mx0 = fmaxf(mx0, __shfl_xor_sync(0xffffffffu, mx0, 1));
        mx0 = fmaxf(mx0, __shfl_xor_sync(0xffffffffu, mx0, 2));
        mx8 = fmaxf(mx8, __shfl_xor_sync(0xffffffffu, mx8, 1));
        mx8 = fmaxf(mx8, __shfl_xor_sync(0xffffffffu, mx8, 2));
        float mn0 = fmaxf(mrow0, mx0), mn8 = fmaxf(mrow8, mx8);
        float fac0 = expf_fast(mrow0 - mn0), fac8 = expf_fast(mrow8 - mn8);
        mrow0 = mn0; mrow8 = mn8;

        float ps0 = 0.f, ps8 = 0.f;
        #pragma unroll
        for (int nf = 0; nf < 4; nf++) {
            sa[nf][0] = expf_fast(sa[nf][0] - mn0);
            sa[nf][1] = expf_fast(sa[nf][1] - mn0);
            sa[nf][2] = expf_fast(sa[nf][2] - mn8);
            sa[nf][3] = expf_fast(sa[nf][3] - mn8);
            ps0 += sa[nf][0] + sa[nf][1];
            ps8 += sa[nf][2] + sa[nf][3];
        }
        ps0 += __shfl_xor_sync(0xffffffffu, ps0, 1);
        ps0 += __shfl_xor_sync(0xffffffffu, ps0, 2);
        ps8 += __shfl_xor_sync(0xffffffffu, ps8, 1);
        ps8 += __shfl_xor_sync(0xffffffffu, ps8, 2);
        lrow0 = lrow0 * fac0 + ps0;
        lrow8 = lrow8 * fac8 + ps8;
        #pragma unroll
        for (int nf = 0; nf < 8; nf++) {
            oa[nf][0] *= fac0; oa[nf][1] *= fac0;
            oa[nf][2] *= fac8; oa[nf][3] *= fac8;
        }

        // O += P V (P split hi/lo in-register)
        #pragma unroll
        for (int ks2 = 0; ks2 < 2; ks2++) {
            uint32_t ph[4], pl[4];
            split2(sa[2*ks2][0],   sa[2*ks2][1],   ph[0], pl[0]);
            split2(sa[2*ks2][2],   sa[2*ks2][3],   ph[1], pl[1]);
            split2(sa[2*ks2+1][0], sa[2*ks2+1][1], ph[2], pl[2]);
            split2(sa[2*ks2+1][2], sa[2*ks2+1][3], ph[3], pl[3]);
            #pragma unroll
            for (int nf4 = 0; nf4 < 4; nf4++) {
                uint32_t vaddr = sb + 9216 + vbase
                               + (uint32_t)(ks2 * 16 * 72 + nf4 * 16) * 2;
                uint32_t vh[4], vl[4];
                lds4t(vh, vaddr);
                lds4t(vl, vaddr + 4608);
                mma16816(oa[2*nf4],   ph, vh);
                mma16816(oa[2*nf4+1], ph, vh + 2);
                mma16816(oa[2*nf4],   ph, vl);
                mma16816(oa[2*nf4+1], ph, vl + 2);
                mma16816(oa[2*nf4],   pl, vh);
                mma16816(oa[2*nf4+1], pl, vh + 2);
            }
        }
        __syncthreads();   // all warps done reading stage s before t+1 refills it
    }

    // epilogue: normalize, q-mask, write token-major xh
    float qm0 = (mask[b * S_ + qr0]     != 0) ? 1.f : 0.f;
    float qm8 = (mask[b * S_ + qr0 + 8] != 0) ? 1.f : 0.f;
    float inv0 = qm0 / lrow0, inv8 = qm8 / lrow8;
    #pragma unroll
    for (int nf = 0; nf < 8; nf++) {
        int col = h * DK_ + 8 * nf + 2 * tig;
        *(float2*)&g_xh[(size_t)(b * S_ + qr0) * HDK_ + col] =
            make_float2(oa[nf][0] * inv0, oa[nf][1] * inv0);
        *(float2*)&g_xh[(size_t)(b * S_ + qr0 + 8) * HDK_ + col] =
            make_float2(oa[nf][2] * inv8, oa[nf][3] * inv8);
    }
}

// ---------------------------------------------------------------------------
// Output GEMM: out = xh @ Wo + bo
// ---------------------------------------------------------------------------
__global__ __launch_bounds__(256, 2) void out_tc_kernel(
    const float* __restrict__ bo, float* __restrict__ out)
{
    extern __shared__ char smc[];
    const uint32_t smb = smem_u32(smc);

    const __nv_bfloat16* WH = g_wh + (size_t)3 * HID_ * HDK_;
    const __nv_bfloat16* WL = g_wl + (size_t)3 * HID_ * HDK_;

    const int m0 = blockIdx.y * 128, n0 = blockIdx.x * 128;
    float acc[2][8][4] = {};
    gemm_main(g_xh, WH, WL, m0, n0, smc, smb, acc);

    const int lane = threadIdx.x & 31, warp = threadIdx.x >> 5;
    const int m0w = (warp >> 1) * 32, n0w = (warp & 1) * 64;
    #pragma unroll
    for (int mf = 0; mf < 2; ++mf) {
        #pragma unroll
        for (int nf = 0; nf < 8; ++nf) {
            const int mr = m0 + m0w + mf * 16 + (lane >> 2);
            const int nn = n0 + n0w + nf * 8 + (lane & 3) * 2;
            const float b0 = bo[nn], b1 = bo[nn + 1];
            *(float2*)&out[(size_t)mr * HDK_ + nn] =
                make_float2(acc[mf][nf][0] + b0, acc[mf][nf][1] + b1);
            *(float2*)&out[(size_t)(mr + 8) * HDK_ + nn] =
                make_float2(acc[mf][nf][2] + b0, acc[mf][nf][3] + b1);
        }
    }
}

// ---------------------------------------------------------------------------
extern "C" void kernel_launch(void* const* d_in, const int* in_sizes, int n_in,
                              void* d_out, int out_size)
{
    const float* q         = (const float*)d_in[0];
    const float* k         = (const float*)d_in[1];
    const float* v         = (const float*)d_in[2];
    const float* attn_bias = (const float*)d_in[3];
    const int*   mask      = (const int*)  d_in[4];
    const float* Wq        = (const float*)d_in[5];
    const float* bq        = (const float*)d_in[6];
    const float* Wk        = (const float*)d_in[7];
    const float* bk        = (const float*)d_in[8];
    const float* Wv        = (const float*)d_in[9];
    const float* bv        = (const float*)d_in[10];
    const float* Wo        = (const float*)d_in[11];
    const float* bo        = (const float*)d_in[12];
    float* out = (float*)d_out;

    static int configured = 0;
    if (!configured) {
        cudaFuncSetAttribute(proj_tc_kernel, cudaFuncAttributeMaxDynamicSharedMemorySize, GSM_BYTES);
        cudaFuncSetAttribute(out_tc_kernel,  cudaFuncAttributeMaxDynamicSharedMemorySize, GSM_BYTES);
        cudaFuncSetAttribute(attn_tc_kernel, cudaFuncAttributeMaxDynamicSharedMemorySize, ATTN_SMEM);
        configured = 1;
    }

    wsplit_kernel<<<dim3(HID_ * HDK_ / 4 / 256, 4), 256>>>(Wq, Wk, Wv, Wo);
    maskprep_kernel<<<(B_ * S_ + 255) / 256, 256>>>(mask);

    proj_tc_kernel<<<dim3(HDK_ / 128, M_ / 128, 3), 256, GSM_BYTES>>>(q, k, v, bq, bk, bv);

    attn_tc_kernel<<<dim3(S_ / 64, H_, B_), 128, ATTN_SMEM>>>(attn_bias, mask);

    out_tc_kernel<<<dim3(HDK_ / 128, M_ / 128), 256, GSM_BYTES>>>(bo, out);
}

// round 6
// speedup vs baseline: 2.8901x; 1.2844x over previous
#include <cuda_runtime.h>
#include <cuda_bf16.h>
#include <cuda_fp16.h>
#include <math.h>
#include <stdint.h>

#define B_    2
#define S_    2048
#define HID_  1024
#define H_    16
#define DK_   64
#define HDK_  1024
#define M_    4096
#define SCALE_ 0.125f
#define NEG_  -1000000000.0f

// Scratch (allocation-free device globals)
__device__ __half g_q16h[B_*H_*S_*DK_], g_q16l[B_*H_*S_*DK_];  // Q fp16 hi/lo
__device__ __half g_k16[B_*H_*S_*DK_];                          // K fp16
__device__ __half g_v16[B_*H_*S_*DK_];                          // V fp16
__device__ float g_xh[M_*HDK_];                 // attention out, token-major
__device__ float g_maskf[B_*S_];                // mask as float 0/1
__device__ __nv_bfloat16 g_wh[4u*HID_*HDK_];    // W hi, [g][k][n]
__device__ __nv_bfloat16 g_wl[4u*HID_*HDK_];    // W lo

// ---------------------------------------------------------------------------
// sm_80-class PTX helpers (harness targets compute_103: no 'a' features)
// ---------------------------------------------------------------------------
__device__ __forceinline__ uint32_t smem_u32(const void* p) {
    uint32_t a;
    asm("{ .reg .u64 t; cvta.to.shared.u64 t, %1; cvt.u32.u64 %0, t; }"
        : "=r"(a) : "l"(p));
    return a;
}
__device__ __forceinline__ void lds4(uint32_t* r, uint32_t addr) {
    asm volatile("ldmatrix.sync.aligned.m8n8.x4.shared.b16 {%0,%1,%2,%3}, [%4];"
                 : "=r"(r[0]), "=r"(r[1]), "=r"(r[2]), "=r"(r[3]) : "r"(addr));
}
__device__ __forceinline__ void lds4t(uint32_t* r, uint32_t addr) {
    asm volatile("ldmatrix.sync.aligned.m8n8.x4.trans.shared.b16 {%0,%1,%2,%3}, [%4];"
                 : "=r"(r[0]), "=r"(r[1]), "=r"(r[2]), "=r"(r[3]) : "r"(addr));
}
// bf16 MMA (GEMMs)
__device__ __forceinline__ void mma16816(float* d, const uint32_t* a, const uint32_t* b) {
    asm volatile(
        "mma.sync.aligned.m16n8k16.row.col.f32.bf16.bf16.f32 "
        "{%0,%1,%2,%3}, {%4,%5,%6,%7}, {%8,%9}, {%0,%1,%2,%3};"
        : "+f"(d[0]), "+f"(d[1]), "+f"(d[2]), "+f"(d[3])
        : "r"(a[0]), "r"(a[1]), "r"(a[2]), "r"(a[3]), "r"(b[0]), "r"(b[1]));
}
// fp16 MMA (attention)
__device__ __forceinline__ void mma16816h(float* d, const uint32_t* a, const uint32_t* b) {
    asm volatile(
        "mma.sync.aligned.m16n8k16.row.col.f32.f16.f16.f32 "
        "{%0,%1,%2,%3}, {%4,%5,%6,%7}, {%8,%9}, {%0,%1,%2,%3};"
        : "+f"(d[0]), "+f"(d[1]), "+f"(d[2]), "+f"(d[3])
        : "r"(a[0]), "r"(a[1]), "r"(a[2]), "r"(a[3]), "r"(b[0]), "r"(b[1]));
}
#define CP_ASYNC16(dst, src) \
    asm volatile("cp.async.cg.shared.global [%0], [%1], 16;" :: "r"(dst), "l"(src))
#define CP_COMMIT() asm volatile("cp.async.commit_group;" ::: "memory")
#define CP_WAIT0()  asm volatile("cp.async.wait_group 0;" ::: "memory")
#define CP_WAIT1()  asm volatile("cp.async.wait_group 1;" ::: "memory")

__device__ __forceinline__ void split2(float a, float b, uint32_t& hi, uint32_t& lo) {
    __nv_bfloat16 ah = __float2bfloat16(a);
    __nv_bfloat16 bh = __float2bfloat16(b);
    __nv_bfloat16 al = __float2bfloat16(a - __bfloat162float(ah));
    __nv_bfloat16 bl = __float2bfloat16(b - __bfloat162float(bh));
    hi = (uint32_t)__bfloat16_as_ushort(ah) | ((uint32_t)__bfloat16_as_ushort(bh) << 16);
    lo = (uint32_t)__bfloat16_as_ushort(al) | ((uint32_t)__bfloat16_as_ushort(bl) << 16);
}
// fp16 hi/lo split
__device__ __forceinline__ void split2h(float a, float b, uint32_t& hi, uint32_t& lo) {
    __half ah = __float2half_rn(a);
    __half bh = __float2half_rn(b);
    __half al = __float2half_rn(a - __half2float(ah));
    __half bl = __float2half_rn(b - __half2float(bh));
    hi = (uint32_t)__half_as_ushort(ah) | ((uint32_t)__half_as_ushort(bh) << 16);
    lo = (uint32_t)__half_as_ushort(al) | ((uint32_t)__half_as_ushort(bl) << 16);
}

// FMA-pipe exp: valid for x in [-inf, ~80]. rel err ~2.4e-6.
__device__ __forceinline__ float expf_fast(float x) {
    float z = fmaxf(x * 1.442695040888963f, -126.0f);
    float r = z + 12582912.0f;
    int   n = __float_as_int(r) - 0x4B400000;
    float f = z - (r - 12582912.0f);
    float gg = f * 0.6931471805599453f;
    float p = fmaf(gg, 0.008333333f, 0.041666667f);
    p = fmaf(gg, p, 0.166666667f);
    p = fmaf(gg, p, 0.5f);
    p = fmaf(gg, p, 1.0f);
    p = fmaf(gg, p, 1.0f);
    return __int_as_float((n + 127) << 23) * p;
}

// ---------------------------------------------------------------------------
// Prep kernels
// ---------------------------------------------------------------------------
__global__ __launch_bounds__(256) void wsplit_kernel(
    const float* __restrict__ Wq, const float* __restrict__ Wk,
    const float* __restrict__ Wv, const float* __restrict__ Wo)
{
    const int g = blockIdx.y;
    const float* W = (g == 0) ? Wq : (g == 1) ? Wk : (g == 2) ? Wv : Wo;
    const int idx = blockIdx.x * 256 + threadIdx.x;
    float4 x = ((const float4*)W)[idx];
    uint32_t h0, l0, h1, l1;
    split2(x.x, x.y, h0, l0);
    split2(x.z, x.w, h1, l1);
    uint2* WH = (uint2*)(g_wh + (size_t)g * HID_ * HDK_);
    uint2* WL = (uint2*)(g_wl + (size_t)g * HID_ * HDK_);
    WH[idx] = make_uint2(h0, h1);
    WL[idx] = make_uint2(l0, l1);
}

__global__ void maskprep_kernel(const int* __restrict__ mask) {
    int i = blockIdx.x * 256 + threadIdx.x;
    if (i < B_ * S_) g_maskf[i] = (mask[i] != 0) ? 1.0f : 0.0f;
}

// ---------------------------------------------------------------------------
// bf16x3 HMMA GEMM core (validated R5). CTA 128x128, 8 warps, K-chunk 16,
// 2-stage smem, 2 CTAs/SM.
// ---------------------------------------------------------------------------
#define A_PAD 24
#define OFF_AL 6144
#define OFF_BH 12288
#define OFF_BL 16640
#define STAGE_ 20992
#define GSM_BYTES (2 * STAGE_)

__device__ __forceinline__ void ldgA(const float* __restrict__ X, int m0, int k0,
                                     int tid, float4* pa) {
    const int r = tid >> 1, c8 = (tid & 1) * 8;
    const float* src = X + (size_t)(m0 + r) * HID_ + k0 + c8;
    pa[0] = *(const float4*)(src);
    pa[1] = *(const float4*)(src + 4);
}
__device__ __forceinline__ void stsA(char* aHp, char* aLp, int tid, const float4* pa) {
    const int r = tid >> 1, c8 = (tid & 1) * 8;
    uint32_t hi[4], lo[4];
    split2(pa[0].x, pa[0].y, hi[0], lo[0]);
    split2(pa[0].z, pa[0].w, hi[1], lo[1]);
    split2(pa[1].x, pa[1].y, hi[2], lo[2]);
    split2(pa[1].z, pa[1].w, hi[3], lo[3]);
    const uint32_t off = (uint32_t)(r * A_PAD + c8) * 2;
    *(uint4*)(aHp + off) = make_uint4(hi[0], hi[1], hi[2], hi[3]);
    *(uint4*)(aLp + off) = make_uint4(lo[0], lo[1], lo[2], lo[3]);
}
__device__ __forceinline__ void cpB(uint32_t bbase,
                                    const __nv_bfloat16* __restrict__ WHp,
                                    const __nv_bfloat16* __restrict__ WLp,
                                    int n0, int k0, int tid) {
    #pragma unroll
    for (int i = 0; i < 2; i++) {
        const int idx = tid + i * 256;
        const int mat = idx >> 8, rem = idx & 255;
        const int row = rem >> 4, c8 = (rem & 15) * 8;
        const size_t g = (size_t)(k0 + row) * HDK_ + n0 + c8;
        const uint32_t d = bbase + mat * 4352 + (uint32_t)(row * 136 + c8) * 2;
        CP_ASYNC16(d, (mat == 0 ? WHp : WLp) + g);
    }
}

__device__ __forceinline__ void gemm_main(
    const float* __restrict__ X,
    const __nv_bfloat16* __restrict__ WH, const __nv_bfloat16* __restrict__ WL,
    int m0, int n0, char* smc, uint32_t smb, float acc[2][8][4])
{
    const int tid  = threadIdx.x;
    const int lane = tid & 31;
    const int warp = tid >> 5;
    const int m0w  = (warp >> 1) * 32;
    const int n0w  = (warp & 1) * 64;
    const int arow = m0w + (lane & 15);
    const int acol = (lane >> 4) * 8;
    const int brow = lane & 15;
    const int bcol = n0w + (lane >> 4) * 8;

    float4 pa[2];
    ldgA(X, m0, 0, tid, pa);
    cpB(smb + OFF_BH, WH, WL, n0, 0, tid);
    CP_COMMIT();
    stsA(smc, smc + OFF_AL, tid, pa);
    CP_WAIT0();
    __syncthreads();

    for (int c = 0; c < 64; ++c) {
        const int s = c & 1;
        const uint32_t sb = smb + s * STAGE_;
        char* scn = smc + (s ^ 1) * STAGE_;

        if (c + 1 < 64) {
            ldgA(X, m0, (c + 1) * 16, tid, pa);
            cpB(smb + (s ^ 1) * STAGE_ + OFF_BH, WH, WL, n0, (c + 1) * 16, tid);
            CP_COMMIT();
        }

        uint32_t ah[2][4], al[2][4];
        #pragma unroll
        for (int mf = 0; mf < 2; ++mf) {
            const uint32_t aoff = (uint32_t)((arow + mf * 16) * A_PAD + acol) * 2;
            lds4(ah[mf], sb + aoff);
            lds4(al[mf], sb + OFF_AL + aoff);
        }
        #pragma unroll
        for (int np = 0; np < 4; ++np) {
            const uint32_t boff = (uint32_t)(brow * 136 + bcol + np * 16) * 2;
            uint32_t bh[4], bl[4];
            lds4t(bh, sb + OFF_BH + boff);
            lds4t(bl, sb + OFF_BL + boff);
            #pragma unroll
            for (int mf = 0; mf < 2; ++mf) {
                mma16816(acc[mf][2*np],   ah[mf], bh);
                mma16816(acc[mf][2*np+1], ah[mf], bh + 2);
                mma16816(acc[mf][2*np],   ah[mf], bl);
                mma16816(acc[mf][2*np+1], ah[mf], bl + 2);
                mma16816(acc[mf][2*np],   al[mf], bh);
                mma16816(acc[mf][2*np+1], al[mf], bh + 2);
            }
        }

        if (c + 1 < 64) stsA(scn, scn + OFF_AL, tid, pa);
        CP_WAIT0();
        __syncthreads();
    }
}

// ---------------------------------------------------------------------------
// Projection GEMMs -> head-major fp16: Q (scaled) hi/lo, K/V single
// ---------------------------------------------------------------------------
__global__ __launch_bounds__(256, 2) void proj_tc_kernel(
    const float* __restrict__ q, const float* __restrict__ k, const float* __restrict__ v,
    const float* __restrict__ bq, const float* __restrict__ bk, const float* __restrict__ bv)
{
    extern __shared__ char smc[];
    const uint32_t smb = smem_u32(smc);

    const int z = blockIdx.z;
    const float* X    = (z == 0) ? q  : (z == 1) ? k  : v;
    const float* bias = (z == 0) ? bq : (z == 1) ? bk : bv;
    const __nv_bfloat16* WH = g_wh + (size_t)z * HID_ * HDK_;
    const __nv_bfloat16* WL = g_wl + (size_t)z * HID_ * HDK_;
    const float osc = (z == 0) ? SCALE_ : 1.0f;

    const int m0 = blockIdx.y * 128, n0 = blockIdx.x * 128;
    float acc[2][8][4] = {};
    gemm_main(X, WH, WL, m0, n0, smc, smb, acc);

    const int lane = threadIdx.x & 31, warp = threadIdx.x >> 5;
    const int m0w = (warp >> 1) * 32, n0w = (warp & 1) * 64;
    #pragma unroll
    for (int mf = 0; mf < 2; ++mf) {
        #pragma unroll
        for (int nf = 0; nf < 8; ++nf) {
            const int mr = m0 + m0w + mf * 16 + (lane >> 2);
            const int nn = n0 + n0w + nf * 8 + (lane & 3) * 2;
            const int hh = nn >> 6, dk = nn & 63;
            const float b0 = bias[nn], b1 = bias[nn + 1];
            #pragma unroll
            for (int rr = 0; rr < 2; ++rr) {
                const int m = mr + rr * 8;
                const int bb = m >> 11, ss = m & 2047;
                float v0 = (acc[mf][nf][2*rr]     + b0) * osc;
                float v1 = (acc[mf][nf][2*rr + 1] + b1) * osc;
                size_t idx = (((size_t)bb * H_ + hh) * S_ + ss) * DK_ + dk;
                if (z == 0) {
                    uint32_t hi, lo;
                    split2h(v0, v1, hi, lo);
                    *(uint32_t*)&g_q16h[idx] = hi;
                    *(uint32_t*)&g_q16l[idx] = lo;
                } else {
                    __half2 hv = __floats2half2_rn(v0, v1);
                    if (z == 1) *(__half2*)&g_k16[idx] = hv;
                    else        *(__half2*)&g_v16[idx] = hv;
                }
            }
        }
    }
}

// ---------------------------------------------------------------------------
// fp16 HMMA flash attention, fixed-reference softmax (m = 0).
// CTA = 64 q-rows of one (b,h), 128 threads (4 warps x m16).
// 64-key tiles; K/V single fp16, 2-stage cp.async. Stage:
//   KH[64][72] 9216 | VH[64][72] 9216 = 18432; x2 stages = 36864.
// ---------------------------------------------------------------------------
#define KV_ST 18432
#define ATTN_SMEM (2 * KV_ST)

__device__ __forceinline__ void cp_kv(uint32_t dstbase,
    const __half* __restrict__ K16, const __half* __restrict__ V16,
    int k0, int tid)
{
    #pragma unroll
    for (int i = 0; i < 8; i++) {
        int idx = tid + i * 128;                 // 1024 chunks (2 mats x 512)
        int mat = idx >> 9, rem = idx & 511;
        int row = rem >> 3, c8 = (rem & 7) * 8;
        const __half* src = ((mat == 0) ? K16 : V16) + (size_t)(k0 + row) * DK_ + c8;
        uint32_t dst = dstbase + mat * 9216 + (uint32_t)(row * 72 + c8) * 2;
        CP_ASYNC16(dst, src);
    }
}

__global__ __launch_bounds__(128, 4) void attn_tc_kernel(
    const float* __restrict__ attn_bias, const int* __restrict__ mask)
{
    extern __shared__ char sm[];
    const uint32_t smb = smem_u32(sm);
    const int tid = threadIdx.x;
    const int lane = tid & 31, warp = tid >> 5;
    const int g = lane >> 2, tig = lane & 3;
    const int q0 = blockIdx.x * 64;
    const int h = blockIdx.y, b = blockIdx.z;

    const size_t hb = ((size_t)b * H_ + h) * S_ * DK_;
    const __half* QHg = g_q16h + hb + (size_t)q0 * DK_;
    const __half* QLg = g_q16l + hb + (size_t)q0 * DK_;
    const __half* K16 = g_k16 + hb;
    const __half* V16 = g_v16 + hb;

    // Q fragments -> registers (mma A-frag layout), loaded once
    uint32_t qh[4][4], ql[4][4];
    {
        const int r0 = warp * 16 + g;
        #pragma unroll
        for (int ks = 0; ks < 4; ks++) {
            const int c = ks * 16 + tig * 2;
            qh[ks][0] = *(const uint32_t*)&QHg[(size_t)r0 * DK_ + c];
            qh[ks][1] = *(const uint32_t*)&QHg[(size_t)(r0 + 8) * DK_ + c];
            qh[ks][2] = *(const uint32_t*)&QHg[(size_t)r0 * DK_ + c + 8];
            qh[ks][3] = *(const uint32_t*)&QHg[(size_t)(r0 + 8) * DK_ + c + 8];
            ql[ks][0] = *(const uint32_t*)&QLg[(size_t)r0 * DK_ + c];
            ql[ks][1] = *(const uint32_t*)&QLg[(size_t)(r0 + 8) * DK_ + c];
            ql[ks][2] = *(const uint32_t*)&QLg[(size_t)r0 * DK_ + c + 8];
            ql[ks][3] = *(const uint32_t*)&QLg[(size_t)(r0 + 8) * DK_ + c + 8];
        }
    }

    cp_kv(smb, K16, V16, 0, tid);
    CP_COMMIT();

    const int qr0 = q0 + warp * 16 + g;
    const float* biasrow = attn_bias + (((size_t)b * H_ + h) * S_ + qr0) * S_;
    const float* mfb = g_maskf + b * S_;

    float oa[8][4] = {};
    float lsum0 = 0.f, lsum8 = 0.f;   // row-sum accumulators (reduced at end)

    const uint32_t kbase = (uint32_t)(((lane & 7) + ((lane & 16) >> 1)) * 72
                                      + (lane & 8)) * 2;
    const uint32_t vbase = (uint32_t)((lane & 15) * 72 + (lane >> 4) * 8) * 2;

    for (int t = 0; t < 32; ++t) {
        const int k0 = t * 64;
        const int s = t & 1;
        const uint32_t sb = smb + s * KV_ST;

        if (t + 1 < 32) {
            cp_kv(smb + (s ^ 1) * KV_ST, K16, V16, (t + 1) * 64, tid);
            CP_COMMIT();
        }

        // bias/mask prefetch into registers
        float2 b0r[8], b1r[8], mr[8];
        #pragma unroll
        for (int nf = 0; nf < 8; nf++) {
            int c = k0 + 8 * nf + 2 * tig;
            b0r[nf] = *(const float2*)&biasrow[c];
            b1r[nf] = *(const float2*)&biasrow[c + 8 * S_];
            mr[nf]  = *(const float2*)&mfb[c];
        }

        if (t + 1 < 32) { CP_WAIT1(); } else { CP_WAIT0(); }
        __syncthreads();

        // S = Q K^T (fp16, q 2-term)
        float sa[8][4];
        #pragma unroll
        for (int i = 0; i < 8; i++)
            #pragma unroll
            for (int j = 0; j < 4; j++) sa[i][j] = 0.f;

        #pragma unroll
        for (int ks = 0; ks < 4; ks++) {
            #pragma unroll
            for (int nf = 0; nf < 4; nf++) {
                uint32_t kaddr = sb + kbase + (uint32_t)(nf * 16 * 72 + ks * 16) * 2;
                uint32_t kh4[4];
                lds4(kh4, kaddr);
                mma16816h(sa[2*nf],   qh[ks], kh4);
                mma16816h(sa[2*nf+1], qh[ks], kh4 + 2);
                mma16816h(sa[2*nf],   ql[ks], kh4);
                mma16816h(sa[2*nf+1], ql[ks], kh4 + 2);
            }
        }

        // mask-select + bias; p = exp(s) (fixed reference max = 0); accumulate row sums
        #pragma unroll
        for (int nf = 0; nf < 8; nf++) {
            sa[nf][0] = expf_fast(((mr[nf].x != 0.f) ? sa[nf][0] : NEG_) + b0r[nf].x);
            sa[nf][1] = expf_fast(((mr[nf].y != 0.f) ? sa[nf][1] : NEG_) + b0r[nf].y);
            sa[nf][2] = expf_fast(((mr[nf].x != 0.f) ? sa[nf][2] : NEG_) + b1r[nf].x);
            sa[nf][3] = expf_fast(((mr[nf].y != 0.f) ? sa[nf][3] : NEG_) + b1r[nf].y);
            lsum0 += sa[nf][0] + sa[nf][1];
            lsum8 += sa[nf][2] + sa[nf][3];
        }

        // O += P V  (p split fp16 hi/lo; v single fp16)
        #pragma unroll
        for (int ks2 = 0; ks2 < 4; ks2++) {
            uint32_t ph[4], pl[4];
            split2h(sa[2*ks2][0],   sa[2*ks2][1],   ph[0], pl[0]);
            split2h(sa[2*ks2][2],   sa[2*ks2][3],   ph[1], pl[1]);
            split2h(sa[2*ks2+1][0], sa[2*ks2+1][1], ph[2], pl[2]);
            split2h(sa[2*ks2+1][2], sa[2*ks2+1][3], ph[3], pl[3]);
            #pragma unroll
            for (int nf4 = 0; nf4 < 4; nf4++) {
                uint32_t vaddr = sb + 9216 + vbase
                               + (uint32_t)(ks2 * 16 * 72 + nf4 * 16) * 2;
                uint32_t vh4[4];
                lds4t(vh4, vaddr);
                mma16816h(oa[2*nf4],   ph, vh4);
                mma16816h(oa[2*nf4+1], ph, vh4 + 2);
                mma16816h(oa[2*nf4],   pl, vh4);
                mma16816h(oa[2*nf4+1], pl, vh4 + 2);
            }
        }
        __syncthreads();   // all warps done with stage s before refill
    }

    // final row-sum reduce (once, not per tile)
    lsum0 += __shfl_xor_sync(0xffffffffu, lsum0, 1);
    lsum0 += __shfl_xor_sync(0xffffffffu, lsum0, 2);
    lsum8 += __shfl_xor_sync(0xffffffffu, lsum8, 1);
    lsum8 += __shfl_xor_sync(0xffffffffu, lsum8, 2);

    // epilogue: normalize, q-mask, write token-major xh
    float qm0 = (mask[b * S_ + qr0]     != 0) ? 1.f : 0.f;
    float qm8 = (mask[b * S_ + qr0 + 8] != 0) ? 1.f : 0.f;
    float inv0 = qm0 / lsum0, inv8 = qm8 / lsum8;
    #pragma unroll
    for (int nf = 0; nf < 8; nf++) {
        int col = h * DK_ + 8 * nf + 2 * tig;
        *(float2*)&g_xh[(size_t)(b * S_ + qr0) * HDK_ + col] =
            make_float2(oa[nf][0] * inv0, oa[nf][1] * inv0);
        *(float2*)&g_xh[(size_t)(b * S_ + qr0 + 8) * HDK_ + col] =
            make_float2(oa[nf][2] * inv8, oa[nf][3] * inv8);
    }
}

// ---------------------------------------------------------------------------
// Output GEMM: out = xh @ Wo + bo
// ---------------------------------------------------------------------------
__global__ __launch_bounds__(256, 2) void out_tc_kernel(
    const float* __restrict__ bo, float* __restrict__ out)
{
    extern __shared__ char smc[];
    const uint32_t smb = smem_u32(smc);

    const __nv_bfloat16* WH = g_wh + (size_t)3 * HID_ * HDK_;
    const __nv_bfloat16* WL = g_wl + (size_t)3 * HID_ * HDK_;

    const int m0 = blockIdx.y * 128, n0 = blockIdx.x * 128;
    float acc[2][8][4] = {};
    gemm_main(g_xh, WH, WL, m0, n0, smc, smb, acc);

    const int lane = threadIdx.x & 31, warp = threadIdx.x >> 5;
    const int m0w = (warp >> 1) * 32, n0w = (warp & 1) * 64;
    #pragma unroll
    for (int mf = 0; mf < 2; ++mf) {
        #pragma unroll
        for (int nf = 0; nf < 8; ++nf) {
            const int mr = m0 + m0w + mf * 16 + (lane >> 2);
            const int nn = n0 + n0w + nf * 8 + (lane & 3) * 2;
            const float b0 = bo[nn], b1 = bo[nn + 1];
            *(float2*)&out[(size_t)mr * HDK_ + nn] =
                make_float2(acc[mf][nf][0] + b0, acc[mf][nf][1] + b1);
            *(float2*)&out[(size_t)(mr + 8) * HDK_ + nn] =
                make_float2(acc[mf][nf][2] + b0, acc[mf][nf][3] + b1);
        }
    }
}

// ---------------------------------------------------------------------------
extern "C" void kernel_launch(void* const* d_in, const int* in_sizes, int n_in,
                              void* d_out, int out_size)
{
    const float* q         = (const float*)d_in[0];
    const float* k         = (const float*)d_in[1];
    const float* v         = (const float*)d_in[2];
    const float* attn_bias = (const float*)d_in[3];
    const int*   mask      = (const int*)  d_in[4];
    const float* Wq        = (const float*)d_in[5];
    const float* bq        = (const float*)d_in[6];
    const float* Wk        = (const float*)d_in[7];
    const float* bk        = (const float*)d_in[8];
    const float* Wv        = (const float*)d_in[9];
    const float* bv        = (const float*)d_in[10];
    const float* Wo        = (const float*)d_in[11];
    const float* bo        = (const float*)d_in[12];
    float* out = (float*)d_out;

    static int configured = 0;
    if (!configured) {
        cudaFuncSetAttribute(proj_tc_kernel, cudaFuncAttributeMaxDynamicSharedMemorySize, GSM_BYTES);
        cudaFuncSetAttribute(out_tc_kernel,  cudaFuncAttributeMaxDynamicSharedMemorySize, GSM_BYTES);
        cudaFuncSetAttribute(attn_tc_kernel, cudaFuncAttributeMaxDynamicSharedMemorySize, ATTN_SMEM);
        configured = 1;
    }

    wsplit_kernel<<<dim3(HID_ * HDK_ / 4 / 256, 4), 256>>>(Wq, Wk, Wv, Wo);
    maskprep_kernel<<<(B_ * S_ + 255) / 256, 256>>>(mask);

    proj_tc_kernel<<<dim3(HDK_ / 128, M_ / 128, 3), 256, GSM_BYTES>>>(q, k, v, bq, bk, bv);

    attn_tc_kernel<<<dim3(S_ / 64, H_, B_), 128, ATTN_SMEM>>>(attn_bias, mask);

    out_tc_kernel<<<dim3(HDK_ / 128, M_ / 128), 256, GSM_BYTES>>>(bo, out);
}

// round 7
// speedup vs baseline: 2.9505x; 1.0209x over previous
#include <cuda_runtime.h>
#include <cuda_bf16.h>
#include <cuda_fp16.h>
#include <math.h>
#include <stdint.h>

#define B_    2
#define S_    2048
#define HID_  1024
#define H_    16
#define DK_   64
#define HDK_  1024
#define M_    4096
#define SCALE_ 0.125f
#define NEG_  -1000000000.0f

// Scratch (allocation-free device globals)
__device__ __half g_q16h[B_*H_*S_*DK_], g_q16l[B_*H_*S_*DK_];  // Q fp16 hi/lo
__device__ __half g_k16[B_*H_*S_*DK_];                          // K fp16
__device__ __half g_v16[B_*H_*S_*DK_];                          // V fp16
__device__ __nv_bfloat16 g_xhh[M_*HDK_], g_xhl[M_*HDK_];        // attn out bf16 hi/lo
__device__ float g_maskf[B_*S_];                                // mask as float 0/1
__device__ __nv_bfloat16 g_wh[4u*HID_*HDK_];                    // W hi, [g][k][n]
__device__ __nv_bfloat16 g_wl[4u*HID_*HDK_];                    // W lo
__device__ __nv_bfloat16 g_insh[3u*M_*HID_], g_insl[3u*M_*HID_]; // q/k/v inputs hi/lo

// ---------------------------------------------------------------------------
// sm_80-class PTX helpers (harness targets compute_103: no 'a' features)
// ---------------------------------------------------------------------------
__device__ __forceinline__ uint32_t smem_u32(const void* p) {
    uint32_t a;
    asm("{ .reg .u64 t; cvta.to.shared.u64 t, %1; cvt.u32.u64 %0, t; }"
        : "=r"(a) : "l"(p));
    return a;
}
__device__ __forceinline__ void lds4(uint32_t* r, uint32_t addr) {
    asm volatile("ldmatrix.sync.aligned.m8n8.x4.shared.b16 {%0,%1,%2,%3}, [%4];"
                 : "=r"(r[0]), "=r"(r[1]), "=r"(r[2]), "=r"(r[3]) : "r"(addr));
}
__device__ __forceinline__ void lds4t(uint32_t* r, uint32_t addr) {
    asm volatile("ldmatrix.sync.aligned.m8n8.x4.trans.shared.b16 {%0,%1,%2,%3}, [%4];"
                 : "=r"(r[0]), "=r"(r[1]), "=r"(r[2]), "=r"(r[3]) : "r"(addr));
}
// bf16 MMA (GEMMs)
__device__ __forceinline__ void mma16816(float* d, const uint32_t* a, const uint32_t* b) {
    asm volatile(
        "mma.sync.aligned.m16n8k16.row.col.f32.bf16.bf16.f32 "
        "{%0,%1,%2,%3}, {%4,%5,%6,%7}, {%8,%9}, {%0,%1,%2,%3};"
        : "+f"(d[0]), "+f"(d[1]), "+f"(d[2]), "+f"(d[3])
        : "r"(a[0]), "r"(a[1]), "r"(a[2]), "r"(a[3]), "r"(b[0]), "r"(b[1]));
}
// fp16 MMA (attention)
__device__ __forceinline__ void mma16816h(float* d, const uint32_t* a, const uint32_t* b) {
    asm volatile(
        "mma.sync.aligned.m16n8k16.row.col.f32.f16.f16.f32 "
        "{%0,%1,%2,%3}, {%4,%5,%6,%7}, {%8,%9}, {%0,%1,%2,%3};"
        : "+f"(d[0]), "+f"(d[1]), "+f"(d[2]), "+f"(d[3])
        : "r"(a[0]), "r"(a[1]), "r"(a[2]), "r"(a[3]), "r"(b[0]), "r"(b[1]));
}
#define CP_ASYNC16(dst, src) \
    asm volatile("cp.async.cg.shared.global [%0], [%1], 16;" :: "r"(dst), "l"(src))
#define CP_COMMIT() asm volatile("cp.async.commit_group;" ::: "memory")
#define CP_WAIT0()  asm volatile("cp.async.wait_group 0;" ::: "memory")
#define CP_WAIT1()  asm volatile("cp.async.wait_group 1;" ::: "memory")

__device__ __forceinline__ void split2(float a, float b, uint32_t& hi, uint32_t& lo) {
    __nv_bfloat16 ah = __float2bfloat16(a);
    __nv_bfloat16 bh = __float2bfloat16(b);
    __nv_bfloat16 al = __float2bfloat16(a - __bfloat162float(ah));
    __nv_bfloat16 bl = __float2bfloat16(b - __bfloat162float(bh));
    hi = (uint32_t)__bfloat16_as_ushort(ah) | ((uint32_t)__bfloat16_as_ushort(bh) << 16);
    lo = (uint32_t)__bfloat16_as_ushort(al) | ((uint32_t)__bfloat16_as_ushort(bl) << 16);
}
__device__ __forceinline__ void split2h(float a, float b, uint32_t& hi, uint32_t& lo) {
    __half ah = __float2half_rn(a);
    __half bh = __float2half_rn(b);
    __half al = __float2half_rn(a - __half2float(ah));
    __half bl = __float2half_rn(b - __half2float(bh));
    hi = (uint32_t)__half_as_ushort(ah) | ((uint32_t)__half_as_ushort(bh) << 16);
    lo = (uint32_t)__half_as_ushort(al) | ((uint32_t)__half_as_ushort(bl) << 16);
}
__device__ __forceinline__ uint32_t pack_h2(float a, float b) {
    __half2 h = __floats2half2_rn(a, b);
    return *(uint32_t*)&h;
}

// FMA-pipe exp, degree-4 (rel err ~4e-5), x <= ~80.
__device__ __forceinline__ float expf_fast(float x) {
    float z = fmaxf(x * 1.442695040888963f, -126.0f);
    float r = z + 12582912.0f;
    int   n = __float_as_int(r) - 0x4B400000;
    float f = z - (r - 12582912.0f);
    float gg = f * 0.6931471805599453f;
    float p = fmaf(gg, 0.041666667f, 0.166666667f);
    p = fmaf(gg, p, 0.5f);
    p = fmaf(gg, p, 1.0f);
    p = fmaf(gg, p, 1.0f);
    return __int_as_float((n + 127) << 23) * p;
}

// ---------------------------------------------------------------------------
// Prep kernels
// ---------------------------------------------------------------------------
__global__ __launch_bounds__(256) void wsplit_kernel(
    const float* __restrict__ Wq, const float* __restrict__ Wk,
    const float* __restrict__ Wv, const float* __restrict__ Wo)
{
    const int g = blockIdx.y;
    const float* W = (g == 0) ? Wq : (g == 1) ? Wk : (g == 2) ? Wv : Wo;
    const int idx = blockIdx.x * 256 + threadIdx.x;
    float4 x = ((const float4*)W)[idx];
    uint32_t h0, l0, h1, l1;
    split2(x.x, x.y, h0, l0);
    split2(x.z, x.w, h1, l1);
    uint2* WH = (uint2*)(g_wh + (size_t)g * HID_ * HDK_);
    uint2* WL = (uint2*)(g_wl + (size_t)g * HID_ * HDK_);
    WH[idx] = make_uint2(h0, h1);
    WL[idx] = make_uint2(l0, l1);
}

__global__ __launch_bounds__(256) void xsplit_kernel(
    const float* __restrict__ q, const float* __restrict__ k, const float* __restrict__ v)
{
    const int g = blockIdx.y;
    const float* X = (g == 0) ? q : (g == 1) ? k : v;
    const int idx = blockIdx.x * 256 + threadIdx.x;
    float4 x = ((const float4*)X)[idx];
    uint32_t h0, l0, h1, l1;
    split2(x.x, x.y, h0, l0);
    split2(x.z, x.w, h1, l1);
    uint2* XH = (uint2*)(g_insh + (size_t)g * M_ * HID_);
    uint2* XL = (uint2*)(g_insl + (size_t)g * M_ * HID_);
    XH[idx] = make_uint2(h0, h1);
    XL[idx] = make_uint2(l0, l1);
}

__global__ void maskprep_kernel(const int* __restrict__ mask) {
    int i = blockIdx.x * 256 + threadIdx.x;
    if (i < B_ * S_) g_maskf[i] = (mask[i] != 0) ? 1.0f : 0.0f;
}

// ---------------------------------------------------------------------------
// bf16x3 HMMA GEMM core: all operands pre-split bf16, full cp.async,
// 3-stage pipeline. CTA 128x128, 8 warps, K-chunk 16, 2 CTAs/SM.
// Stage: AH[128][24] 6144 | AL 6144 | BH[16][136] 4352 | BL 4352 = 20992.
// ---------------------------------------------------------------------------
#define A_PAD 24
#define OFF_AL 6144
#define OFF_BH 12288
#define OFF_BL 16640
#define STAGE_ 20992
#define GSM_BYTES (3 * STAGE_)

__device__ __forceinline__ void cpA(uint32_t abase,
                                    const __nv_bfloat16* __restrict__ XH,
                                    const __nv_bfloat16* __restrict__ XL,
                                    int m0, int k0, int tid) {
    #pragma unroll
    for (int i = 0; i < 2; i++) {
        const int idx = tid + i * 256;           // 512 chunks (2 mats x 256)
        const int mat = idx >> 8, rem = idx & 255;
        const int row = rem >> 1, c8 = (rem & 1) * 8;
        const size_t g = (size_t)(m0 + row) * HID_ + k0 + c8;
        const uint32_t d = abase + mat * OFF_AL + (uint32_t)(row * A_PAD + c8) * 2;
        CP_ASYNC16(d, (mat == 0 ? XH : XL) + g);
    }
}
__device__ __forceinline__ void cpB(uint32_t bbase,
                                    const __nv_bfloat16* __restrict__ WHp,
                                    const __nv_bfloat16* __restrict__ WLp,
                                    int n0, int k0, int tid) {
    #pragma unroll
    for (int i = 0; i < 2; i++) {
        const int idx = tid + i * 256;           // 512 chunks (2 mats x 256)
        const int mat = idx >> 8, rem = idx & 255;
        const int row = rem >> 4, c8 = (rem & 15) * 8;
        const size_t g = (size_t)(k0 + row) * HDK_ + n0 + c8;
        const uint32_t d = bbase + mat * 4352 + (uint32_t)(row * 136 + c8) * 2;
        CP_ASYNC16(d, (mat == 0 ? WHp : WLp) + g);
    }
}

__device__ __forceinline__ void gemm_main(
    const __nv_bfloat16* __restrict__ XH, const __nv_bfloat16* __restrict__ XL,
    const __nv_bfloat16* __restrict__ WH, const __nv_bfloat16* __restrict__ WL,
    int m0, int n0, uint32_t smb, float acc[2][8][4])
{
    const int tid  = threadIdx.x;
    const int lane = tid & 31;
    const int warp = tid >> 5;
    const int m0w  = (warp >> 1) * 32;
    const int n0w  = (warp & 1) * 64;
    const int arow = m0w + (lane & 15);
    const int acol = (lane >> 4) * 8;
    const int brow = lane & 15;
    const int bcol = n0w + (lane >> 4) * 8;

    // Prologue: stages 0,1
    cpA(smb, XH, XL, m0, 0, tid);
    cpB(smb + OFF_BH, WH, WL, n0, 0, tid);
    CP_COMMIT();
    cpA(smb + STAGE_, XH, XL, m0, 16, tid);
    cpB(smb + STAGE_ + OFF_BH, WH, WL, n0, 16, tid);
    CP_COMMIT();

    int sidx = 0;   // stage of chunk c (c % 3)
    for (int c = 0; c < 64; ++c) {
        if (c + 1 < 64) { CP_WAIT1(); } else { CP_WAIT0(); }
        __syncthreads();
        const uint32_t sb = smb + sidx * STAGE_;

        if (c + 2 < 64) {
            const int pidx = (sidx + 2 >= 3) ? sidx - 1 : sidx + 2;
            const uint32_t nb = smb + pidx * STAGE_;
            cpA(nb, XH, XL, m0, (c + 2) * 16, tid);
            cpB(nb + OFF_BH, WH, WL, n0, (c + 2) * 16, tid);
            CP_COMMIT();
        }
        sidx = (sidx + 1 >= 3) ? 0 : sidx + 1;

        uint32_t ah[2][4], al[2][4];
        #pragma unroll
        for (int mf = 0; mf < 2; ++mf) {
            const uint32_t aoff = (uint32_t)((arow + mf * 16) * A_PAD + acol) * 2;
            lds4(ah[mf], sb + aoff);
            lds4(al[mf], sb + OFF_AL + aoff);
        }
        #pragma unroll
        for (int np = 0; np < 4; ++np) {
            const uint32_t boff = (uint32_t)(brow * 136 + bcol + np * 16) * 2;
            uint32_t bh[4], bl[4];
            lds4t(bh, sb + OFF_BH + boff);
            lds4t(bl, sb + OFF_BL + boff);
            #pragma unroll
            for (int mf = 0; mf < 2; ++mf) {
                mma16816(acc[mf][2*np],   ah[mf], bh);
                mma16816(acc[mf][2*np+1], ah[mf], bh + 2);
                mma16816(acc[mf][2*np],   ah[mf], bl);
                mma16816(acc[mf][2*np+1], ah[mf], bl + 2);
                mma16816(acc[mf][2*np],   al[mf], bh);
                mma16816(acc[mf][2*np+1], al[mf], bh + 2);
            }
        }
    }
}

// ---------------------------------------------------------------------------
// Projection GEMMs -> head-major fp16: Q (scaled) hi/lo, K/V single
// ---------------------------------------------------------------------------
__global__ __launch_bounds__(256, 2) void proj_tc_kernel(
    const float* __restrict__ bq, const float* __restrict__ bk, const float* __restrict__ bv)
{
    extern __shared__ char smc[];
    const uint32_t smb = smem_u32(smc);

    const int z = blockIdx.z;
    const float* bias = (z == 0) ? bq : (z == 1) ? bk : bv;
    const __nv_bfloat16* XH = g_insh + (size_t)z * M_ * HID_;
    const __nv_bfloat16* XL = g_insl + (size_t)z * M_ * HID_;
    const __nv_bfloat16* WH = g_wh + (size_t)z * HID_ * HDK_;
    const __nv_bfloat16* WL = g_wl + (size_t)z * HID_ * HDK_;
    const float osc = (z == 0) ? SCALE_ : 1.0f;

    const int m0 = blockIdx.y * 128, n0 = blockIdx.x * 128;
    float acc[2][8][4] = {};
    gemm_main(XH, XL, WH, WL, m0, n0, smb, acc);

    const int lane = threadIdx.x & 31, warp = threadIdx.x >> 5;
    const int m0w = (warp >> 1) * 32, n0w = (warp & 1) * 64;
    #pragma unroll
    for (int mf = 0; mf < 2; ++mf) {
        #pragma unroll
        for (int nf = 0; nf < 8; ++nf) {
            const int mr = m0 + m0w + mf * 16 + (lane >> 2);
            const int nn = n0 + n0w + nf * 8 + (lane & 3) * 2;
            const int hh = nn >> 6, dk = nn & 63;
            const float b0 = bias[nn], b1 = bias[nn + 1];
            #pragma unroll
            for (int rr = 0; rr < 2; ++rr) {
                const int m = mr + rr * 8;
                const int bb = m >> 11, ss = m & 2047;
                float v0 = (acc[mf][nf][2*rr]     + b0) * osc;
                float v1 = (acc[mf][nf][2*rr + 1] + b1) * osc;
                size_t idx = (((size_t)bb * H_ + hh) * S_ + ss) * DK_ + dk;
                if (z == 0) {
                    uint32_t hi, lo;
                    split2h(v0, v1, hi, lo);
                    *(uint32_t*)&g_q16h[idx] = hi;
                    *(uint32_t*)&g_q16l[idx] = lo;
                } else {
                    uint32_t hv = pack_h2(v0, v1);
                    if (z == 1) *(uint32_t*)&g_k16[idx] = hv;
                    else        *(uint32_t*)&g_v16[idx] = hv;
                }
            }
        }
    }
}

// ---------------------------------------------------------------------------
// fp16 HMMA flash attention, fixed-reference softmax (m = 0).
// CTA = 64 q-rows of one (b,h), 128 threads (4 warps x m16).
// 64-key tiles; Q 2-term fp16 (regs), K single, P single, V single.
// Stage: KH[64][72] 9216 | VH[64][72] 9216 = 18432; x2 = 36864.
// ---------------------------------------------------------------------------
#define KV_ST 18432
#define ATTN_SMEM (2 * KV_ST)

__device__ __forceinline__ void cp_kv(uint32_t dstbase,
    const __half* __restrict__ K16, const __half* __restrict__ V16,
    int k0, int tid)
{
    #pragma unroll
    for (int i = 0; i < 8; i++) {
        int idx = tid + i * 128;                 // 1024 chunks (2 mats x 512)
        int mat = idx >> 9, rem = idx & 511;
        int row = rem >> 3, c8 = (rem & 7) * 8;
        const __half* src = ((mat == 0) ? K16 : V16) + (size_t)(k0 + row) * DK_ + c8;
        uint32_t dst = dstbase + mat * 9216 + (uint32_t)(row * 72 + c8) * 2;
        CP_ASYNC16(dst, src);
    }
}

__global__ __launch_bounds__(128, 4) void attn_tc_kernel(
    const float* __restrict__ attn_bias, const int* __restrict__ mask)
{
    extern __shared__ char sm[];
    const uint32_t smb = smem_u32(sm);
    const int tid = threadIdx.x;
    const int lane = tid & 31, warp = tid >> 5;
    const int g = lane >> 2, tig = lane & 3;
    const int q0 = blockIdx.x * 64;
    const int h = blockIdx.y, b = blockIdx.z;

    const size_t hb = ((size_t)b * H_ + h) * S_ * DK_;
    const __half* QHg = g_q16h + hb + (size_t)q0 * DK_;
    const __half* QLg = g_q16l + hb + (size_t)q0 * DK_;
    const __half* K16 = g_k16 + hb;
    const __half* V16 = g_v16 + hb;

    // Q fragments -> registers (mma A-frag layout), loaded once
    uint32_t qh[4][4], ql[4][4];
    {
        const int r0 = warp * 16 + g;
        #pragma unroll
        for (int ks = 0; ks < 4; ks++) {
            const int c = ks * 16 + tig * 2;
            qh[ks][0] = *(const uint32_t*)&QHg[(size_t)r0 * DK_ + c];
            qh[ks][1] = *(const uint32_t*)&QHg[(size_t)(r0 + 8) * DK_ + c];
            qh[ks][2] = *(const uint32_t*)&QHg[(size_t)r0 * DK_ + c + 8];
            qh[ks][3] = *(const uint32_t*)&QHg[(size_t)(r0 + 8) * DK_ + c + 8];
            ql[ks][0] = *(const uint32_t*)&QLg[(size_t)r0 * DK_ + c];
            ql[ks][1] = *(const uint32_t*)&QLg[(size_t)(r0 + 8) * DK_ + c];
            ql[ks][2] = *(const uint32_t*)&QLg[(size_t)r0 * DK_ + c + 8];
            ql[ks][3] = *(const uint32_t*)&QLg[(size_t)(r0 + 8) * DK_ + c + 8];
        }
    }

    cp_kv(smb, K16, V16, 0, tid);
    CP_COMMIT();

    const int qr0 = q0 + warp * 16 + g;
    const float* biasrow = attn_bias + (((size_t)b * H_ + h) * S_ + qr0) * S_;
    const float* mfb = g_maskf + b * S_;

    float oa[8][4] = {};
    float lsum0 = 0.f, lsum8 = 0.f;

    const uint32_t kbase = (uint32_t)(((lane & 7) + ((lane & 16) >> 1)) * 72
                                      + (lane & 8)) * 2;
    const uint32_t vbase = (uint32_t)((lane & 15) * 72 + (lane >> 4) * 8) * 2;

    for (int t = 0; t < 32; ++t) {
        const int k0 = t * 64;
        const int s = t & 1;
        const uint32_t sb = smb + s * KV_ST;

        if (t + 1 < 32) {
            cp_kv(smb + (s ^ 1) * KV_ST, K16, V16, (t + 1) * 64, tid);
            CP_COMMIT();
        }

        float2 b0r[8], b1r[8], mr[8];
        #pragma unroll
        for (int nf = 0; nf < 8; nf++) {
            int c = k0 + 8 * nf + 2 * tig;
            b0r[nf] = *(const float2*)&biasrow[c];
            b1r[nf] = *(const float2*)&biasrow[c + 8 * S_];
            mr[nf]  = *(const float2*)&mfb[c];
        }

        if (t + 1 < 32) { CP_WAIT1(); } else { CP_WAIT0(); }
        __syncthreads();

        // S = Q K^T (fp16, Q 2-term)
        float sa[8][4];
        #pragma unroll
        for (int i = 0; i < 8; i++)
            #pragma unroll
            for (int j = 0; j < 4; j++) sa[i][j] = 0.f;

        #pragma unroll
        for (int ks = 0; ks < 4; ks++) {
            #pragma unroll
            for (int nf = 0; nf < 4; nf++) {
                uint32_t kaddr = sb + kbase + (uint32_t)(nf * 16 * 72 + ks * 16) * 2;
                uint32_t kh4[4];
                lds4(kh4, kaddr);
                mma16816h(sa[2*nf],   qh[ks], kh4);
                mma16816h(sa[2*nf+1], qh[ks], kh4 + 2);
                mma16816h(sa[2*nf],   ql[ks], kh4);
                mma16816h(sa[2*nf+1], ql[ks], kh4 + 2);
            }
        }

        // mask-select + bias; p = exp(s) fixed-ref; accumulate row sums
        #pragma unroll
        for (int nf = 0; nf < 8; nf++) {
            sa[nf][0] = expf_fast(((mr[nf].x != 0.f) ? sa[nf][0] : NEG_) + b0r[nf].x);
            sa[nf][1] = expf_fast(((mr[nf].y != 0.f) ? sa[nf][1] : NEG_) + b0r[nf].y);
            sa[nf][2] = expf_fast(((mr[nf].x != 0.f) ? sa[nf][2] : NEG_) + b1r[nf].x);
            sa[nf][3] = expf_fast(((mr[nf].y != 0.f) ? sa[nf][3] : NEG_) + b1r[nf].y);
            lsum0 += sa[nf][0] + sa[nf][1];
            lsum8 += sa[nf][2] + sa[nf][3];
        }

        // O += P V (P single fp16, V single fp16)
        #pragma unroll
        for (int ks2 = 0; ks2 < 4; ks2++) {
            uint32_t ph[4];
            ph[0] = pack_h2(sa[2*ks2][0],   sa[2*ks2][1]);
            ph[1] = pack_h2(sa[2*ks2][2],   sa[2*ks2][3]);
            ph[2] = pack_h2(sa[2*ks2+1][0], sa[2*ks2+1][1]);
            ph[3] = pack_h2(sa[2*ks2+1][2], sa[2*ks2+1][3]);
            #pragma unroll
            for (int nf4 = 0; nf4 < 4; nf4++) {
                uint32_t vaddr = sb + 9216 + vbase
                               + (uint32_t)(ks2 * 16 * 72 + nf4 * 16) * 2;
                uint32_t vh4[4];
                lds4t(vh4, vaddr);
                mma16816h(oa[2*nf4],   ph, vh4);
                mma16816h(oa[2*nf4+1], ph, vh4 + 2);
            }
        }
        __syncthreads();
    }

    // final row-sum reduce
    lsum0 += __shfl_xor_sync(0xffffffffu, lsum0, 1);
    lsum0 += __shfl_xor_sync(0xffffffffu, lsum0, 2);
    lsum8 += __shfl_xor_sync(0xffffffffu, lsum8, 1);
    lsum8 += __shfl_xor_sync(0xffffffffu, lsum8, 2);

    // epilogue: normalize, q-mask, write bf16 hi/lo token-major xh
    float qm0 = (mask[b * S_ + qr0]     != 0) ? 1.f : 0.f;
    float qm8 = (mask[b * S_ + qr0 + 8] != 0) ? 1.f : 0.f;
    float inv0 = qm0 / lsum0, inv8 = qm8 / lsum8;
    #pragma unroll
    for (int nf = 0; nf < 8; nf++) {
        int col = h * DK_ + 8 * nf + 2 * tig;
        uint32_t hi, lo;
        split2(oa[nf][0] * inv0, oa[nf][1] * inv0, hi, lo);
        size_t i0 = (size_t)(b * S_ + qr0) * HDK_ + col;
        *(uint32_t*)&g_xhh[i0] = hi;
        *(uint32_t*)&g_xhl[i0] = lo;
        split2(oa[nf][2] * inv8, oa[nf][3] * inv8, hi, lo);
        size_t i8 = (size_t)(b * S_ + qr0 + 8) * HDK_ + col;
        *(uint32_t*)&g_xhh[i8] = hi;
        *(uint32_t*)&g_xhl[i8] = lo;
    }
}

// ---------------------------------------------------------------------------
// Output GEMM: out = xh @ Wo + bo
// ---------------------------------------------------------------------------
__global__ __launch_bounds__(256, 2) void out_tc_kernel(
    const float* __restrict__ bo, float* __restrict__ out)
{
    extern __shared__ char smc[];
    const uint32_t smb = smem_u32(smc);

    const __nv_bfloat16* WH = g_wh + (size_t)3 * HID_ * HDK_;
    const __nv_bfloat16* WL = g_wl + (size_t)3 * HID_ * HDK_;

    const int m0 = blockIdx.y * 128, n0 = blockIdx.x * 128;
    float acc[2][8][4] = {};
    gemm_main(g_xhh, g_xhl, WH, WL, m0, n0, smb, acc);

    const int lane = threadIdx.x & 31, warp = threadIdx.x >> 5;
    const int m0w = (warp >> 1) * 32, n0w = (warp & 1) * 64;
    #pragma unroll
    for (int mf = 0; mf < 2; ++mf) {
        #pragma unroll
        for (int nf = 0; nf < 8; ++nf) {
            const int mr = m0 + m0w + mf * 16 + (lane >> 2);
            const int nn = n0 + n0w + nf * 8 + (lane & 3) * 2;
            const float b0 = bo[nn], b1 = bo[nn + 1];
            *(float2*)&out[(size_t)mr * HDK_ + nn] =
                make_float2(acc[mf][nf][0] + b0, acc[mf][nf][1] + b1);
            *(float2*)&out[(size_t)(mr + 8) * HDK_ + nn] =
                make_float2(acc[mf][nf][2] + b0, acc[mf][nf][3] + b1);
        }
    }
}

// ---------------------------------------------------------------------------
extern "C" void kernel_launch(void* const* d_in, const int* in_sizes, int n_in,
                              void* d_out, int out_size)
{
    const float* q         = (const float*)d_in[0];
    const float* k         = (const float*)d_in[1];
    const float* v         = (const float*)d_in[2];
    const float* attn_bias = (const float*)d_in[3];
    const int*   mask      = (const int*)  d_in[4];
    const float* bq        = (const float*)d_in[6];
    const float* bk        = (const float*)d_in[8];
    const float* bv        = (const float*)d_in[10];
    const float* Wq        = (const float*)d_in[5];
    const float* Wk        = (const float*)d_in[7];
    const float* Wv        = (const float*)d_in[9];
    const float* Wo        = (const float*)d_in[11];
    const float* bo        = (const float*)d_in[12];
    float* out = (float*)d_out;

    static int configured = 0;
    if (!configured) {
        cudaFuncSetAttribute(proj_tc_kernel, cudaFuncAttributeMaxDynamicSharedMemorySize, GSM_BYTES);
        cudaFuncSetAttribute(out_tc_kernel,  cudaFuncAttributeMaxDynamicSharedMemorySize, GSM_BYTES);
        cudaFuncSetAttribute(attn_tc_kernel, cudaFuncAttributeMaxDynamicSharedMemorySize, ATTN_SMEM);
        configured = 1;
    }

    wsplit_kernel<<<dim3(HID_ * HDK_ / 4 / 256, 4), 256>>>(Wq, Wk, Wv, Wo);
    xsplit_kernel<<<dim3(M_ * HID_ / 4 / 256, 3), 256>>>(q, k, v);
    maskprep_kernel<<<(B_ * S_ + 255) / 256, 256>>>(mask);

    proj_tc_kernel<<<dim3(HDK_ / 128, M_ / 128, 3), 256, GSM_BYTES>>>(bq, bk, bv);

    attn_tc_kernel<<<dim3(S_ / 64, H_, B_), 128, ATTN_SMEM>>>(attn_bias, mask);

    out_tc_kernel<<<dim3(HDK_ / 128, M_ / 128), 256, GSM_BYTES>>>(bo, out);
}

// round 8
// speedup vs baseline: 3.2844x; 1.1131x over previous
#include <cuda_runtime.h>
#include <cuda_bf16.h>
#include <cuda_fp16.h>
#include <math.h>
#include <stdint.h>

#define B_    2
#define S_    2048
#define HID_  1024
#define H_    16
#define DK_   64
#define HDK_  1024
#define M_    4096
#define SCALE_ 0.125f
#define NEG_  -1000000000.0f

// Scratch (allocation-free device globals)
__device__ __half g_q16[B_*H_*S_*DK_];                          // Q fp16 (scaled)
__device__ __half g_k16[B_*H_*S_*DK_];                          // K fp16
__device__ __half g_v16[B_*H_*S_*DK_];                          // V fp16
__device__ __nv_bfloat16 g_xhh[M_*HDK_], g_xhl[M_*HDK_];        // attn out bf16 hi/lo
__device__ float g_maskf[B_*S_];                                // mask as float 0/1
__device__ __nv_bfloat16 g_wh[4u*HID_*HDK_];                    // W hi, [g][k][n]
__device__ __nv_bfloat16 g_wl[4u*HID_*HDK_];                    // W lo
__device__ __nv_bfloat16 g_insh[3u*M_*HID_], g_insl[3u*M_*HID_]; // q/k/v inputs hi/lo

// ---------------------------------------------------------------------------
// sm_80-class PTX helpers (harness targets compute_103: no 'a' features)
// ---------------------------------------------------------------------------
__device__ __forceinline__ uint32_t smem_u32(const void* p) {
    uint32_t a;
    asm("{ .reg .u64 t; cvta.to.shared.u64 t, %1; cvt.u32.u64 %0, t; }"
        : "=r"(a) : "l"(p));
    return a;
}
__device__ __forceinline__ void lds4(uint32_t* r, uint32_t addr) {
    asm volatile("ldmatrix.sync.aligned.m8n8.x4.shared.b16 {%0,%1,%2,%3}, [%4];"
                 : "=r"(r[0]), "=r"(r[1]), "=r"(r[2]), "=r"(r[3]) : "r"(addr));
}
__device__ __forceinline__ void lds4t(uint32_t* r, uint32_t addr) {
    asm volatile("ldmatrix.sync.aligned.m8n8.x4.trans.shared.b16 {%0,%1,%2,%3}, [%4];"
                 : "=r"(r[0]), "=r"(r[1]), "=r"(r[2]), "=r"(r[3]) : "r"(addr));
}
// bf16 MMA (GEMMs)
__device__ __forceinline__ void mma16816(float* d, const uint32_t* a, const uint32_t* b) {
    asm volatile(
        "mma.sync.aligned.m16n8k16.row.col.f32.bf16.bf16.f32 "
        "{%0,%1,%2,%3}, {%4,%5,%6,%7}, {%8,%9}, {%0,%1,%2,%3};"
        : "+f"(d[0]), "+f"(d[1]), "+f"(d[2]), "+f"(d[3])
        : "r"(a[0]), "r"(a[1]), "r"(a[2]), "r"(a[3]), "r"(b[0]), "r"(b[1]));
}
// fp16 MMA (attention)
__device__ __forceinline__ void mma16816h(float* d, const uint32_t* a, const uint32_t* b) {
    asm volatile(
        "mma.sync.aligned.m16n8k16.row.col.f32.f16.f16.f32 "
        "{%0,%1,%2,%3}, {%4,%5,%6,%7}, {%8,%9}, {%0,%1,%2,%3};"
        : "+f"(d[0]), "+f"(d[1]), "+f"(d[2]), "+f"(d[3])
        : "r"(a[0]), "r"(a[1]), "r"(a[2]), "r"(a[3]), "r"(b[0]), "r"(b[1]));
}
#define CP_ASYNC16(dst, src) \
    asm volatile("cp.async.cg.shared.global [%0], [%1], 16;" :: "r"(dst), "l"(src))
#define CP_COMMIT() asm volatile("cp.async.commit_group;" ::: "memory")
#define CP_WAIT0()  asm volatile("cp.async.wait_group 0;" ::: "memory")
#define CP_WAIT1()  asm volatile("cp.async.wait_group 1;" ::: "memory")
#define CP_WAIT2()  asm volatile("cp.async.wait_group 2;" ::: "memory")

__device__ __forceinline__ void split2(float a, float b, uint32_t& hi, uint32_t& lo) {
    __nv_bfloat16 ah = __float2bfloat16(a);
    __nv_bfloat16 bh = __float2bfloat16(b);
    __nv_bfloat16 al = __float2bfloat16(a - __bfloat162float(ah));
    __nv_bfloat16 bl = __float2bfloat16(b - __bfloat162float(bh));
    hi = (uint32_t)__bfloat16_as_ushort(ah) | ((uint32_t)__bfloat16_as_ushort(bh) << 16);
    lo = (uint32_t)__bfloat16_as_ushort(al) | ((uint32_t)__bfloat16_as_ushort(bl) << 16);
}
__device__ __forceinline__ uint32_t pack_h2(float a, float b) {
    __half2 h = __floats2half2_rn(a, b);
    return *(uint32_t*)&h;
}

// FMA-pipe exp, degree-4 (rel err ~4e-5), x <= ~80.
__device__ __forceinline__ float expf_fast(float x) {
    float z = fmaxf(x * 1.442695040888963f, -126.0f);
    float r = z + 12582912.0f;
    int   n = __float_as_int(r) - 0x4B400000;
    float f = z - (r - 12582912.0f);
    float gg = f * 0.6931471805599453f;
    float p = fmaf(gg, 0.041666667f, 0.166666667f);
    p = fmaf(gg, p, 0.5f);
    p = fmaf(gg, p, 1.0f);
    p = fmaf(gg, p, 1.0f);
    return __int_as_float((n + 127) << 23) * p;
}

// ---------------------------------------------------------------------------
// Prep: merged weight + input hi/lo split (y: 0-3 = W, 4-6 = q/k/v inputs)
// ---------------------------------------------------------------------------
__global__ __launch_bounds__(256) void prep_kernel(
    const float* __restrict__ q, const float* __restrict__ k, const float* __restrict__ v,
    const float* __restrict__ Wq, const float* __restrict__ Wk,
    const float* __restrict__ Wv, const float* __restrict__ Wo)
{
    const int g = blockIdx.y;
    const int idx = blockIdx.x * 256 + threadIdx.x;
    const float* src;
    uint2 *DH, *DL;
    if (g < 4) {
        if (idx >= HID_ * HDK_ / 4) return;
        src = (g == 0) ? Wq : (g == 1) ? Wk : (g == 2) ? Wv : Wo;
        DH = (uint2*)(g_wh + (size_t)g * HID_ * HDK_);
        DL = (uint2*)(g_wl + (size_t)g * HID_ * HDK_);
    } else {
        src = (g == 4) ? q : (g == 5) ? k : v;
        DH = (uint2*)(g_insh + (size_t)(g - 4) * M_ * HID_);
        DL = (uint2*)(g_insl + (size_t)(g - 4) * M_ * HID_);
    }
    float4 x = ((const float4*)src)[idx];
    uint32_t h0, l0, h1, l1;
    split2(x.x, x.y, h0, l0);
    split2(x.z, x.w, h1, l1);
    DH[idx] = make_uint2(h0, h1);
    DL[idx] = make_uint2(l0, l1);
}

__global__ void maskprep_kernel(const int* __restrict__ mask) {
    int i = blockIdx.x * 256 + threadIdx.x;
    if (i < B_ * S_) g_maskf[i] = (mask[i] != 0) ? 1.0f : 0.0f;
}

// ---------------------------------------------------------------------------
// bf16x3 HMMA GEMM core: all operands pre-split bf16, full cp.async,
// 4-stage pipeline (prefetch distance 3). CTA 128x128, 8 warps, K-chunk 16,
// 2 CTAs/SM. Stage: AH[128][24] 6144 | AL 6144 | BH[16][136] 4352 | BL 4352.
// ---------------------------------------------------------------------------
#define A_PAD 24
#define OFF_AL 6144
#define OFF_BH 12288
#define OFF_BL 16640
#define STAGE_ 20992
#define GSM_BYTES (4 * STAGE_)

__device__ __forceinline__ void cpA(uint32_t abase,
                                    const __nv_bfloat16* __restrict__ XH,
                                    const __nv_bfloat16* __restrict__ XL,
                                    int m0, int k0, int tid) {
    #pragma unroll
    for (int i = 0; i < 2; i++) {
        const int idx = tid + i * 256;           // 512 chunks (2 mats x 256)
        const int mat = idx >> 8, rem = idx & 255;
        const int row = rem >> 1, c8 = (rem & 1) * 8;
        const size_t g = (size_t)(m0 + row) * HID_ + k0 + c8;
        const uint32_t d = abase + mat * OFF_AL + (uint32_t)(row * A_PAD + c8) * 2;
        CP_ASYNC16(d, (mat == 0 ? XH : XL) + g);
    }
}
__device__ __forceinline__ void cpB(uint32_t bbase,
                                    const __nv_bfloat16* __restrict__ WHp,
                                    const __nv_bfloat16* __restrict__ WLp,
                                    int n0, int k0, int tid) {
    #pragma unroll
    for (int i = 0; i < 2; i++) {
        const int idx = tid + i * 256;           // 512 chunks (2 mats x 256)
        const int mat = idx >> 8, rem = idx & 255;
        const int row = rem >> 4, c8 = (rem & 15) * 8;
        const size_t g = (size_t)(k0 + row) * HDK_ + n0 + c8;
        const uint32_t d = bbase + mat * 4352 + (uint32_t)(row * 136 + c8) * 2;
        CP_ASYNC16(d, (mat == 0 ? WHp : WLp) + g);
    }
}

__device__ __forceinline__ void gemm_main(
    const __nv_bfloat16* __restrict__ XH, const __nv_bfloat16* __restrict__ XL,
    const __nv_bfloat16* __restrict__ WH, const __nv_bfloat16* __restrict__ WL,
    int m0, int n0, uint32_t smb, float acc[2][8][4])
{
    const int tid  = threadIdx.x;
    const int lane = tid & 31;
    const int warp = tid >> 5;
    const int m0w  = (warp >> 1) * 32;
    const int n0w  = (warp & 1) * 64;
    const int arow = m0w + (lane & 15);
    const int acol = (lane >> 4) * 8;
    const int brow = lane & 15;
    const int bcol = n0w + (lane >> 4) * 8;

    // Prologue: chunks 0,1,2 -> stages 0,1,2
    #pragma unroll
    for (int pc = 0; pc < 3; ++pc) {
        cpA(smb + pc * STAGE_, XH, XL, m0, pc * 16, tid);
        cpB(smb + pc * STAGE_ + OFF_BH, WH, WL, n0, pc * 16, tid);
        CP_COMMIT();
    }

    for (int c = 0; c < 64; ++c) {
        if (c <= 61) { CP_WAIT2(); } else if (c == 62) { CP_WAIT1(); } else { CP_WAIT0(); }
        __syncthreads();
        const uint32_t sb = smb + (uint32_t)(c & 3) * STAGE_;

        if (c + 3 < 64) {
            const uint32_t nb = smb + (uint32_t)((c + 3) & 3) * STAGE_;
            cpA(nb, XH, XL, m0, (c + 3) * 16, tid);
            cpB(nb + OFF_BH, WH, WL, n0, (c + 3) * 16, tid);
            CP_COMMIT();
        }

        uint32_t ah[2][4], al[2][4];
        #pragma unroll
        for (int mf = 0; mf < 2; ++mf) {
            const uint32_t aoff = (uint32_t)((arow + mf * 16) * A_PAD + acol) * 2;
            lds4(ah[mf], sb + aoff);
            lds4(al[mf], sb + OFF_AL + aoff);
        }
        #pragma unroll
        for (int np = 0; np < 4; ++np) {
            const uint32_t boff = (uint32_t)(brow * 136 + bcol + np * 16) * 2;
            uint32_t bh[4], bl[4];
            lds4t(bh, sb + OFF_BH + boff);
            lds4t(bl, sb + OFF_BL + boff);
            #pragma unroll
            for (int mf = 0; mf < 2; ++mf) {
                mma16816(acc[mf][2*np],   ah[mf], bh);
                mma16816(acc[mf][2*np+1], ah[mf], bh + 2);
                mma16816(acc[mf][2*np],   ah[mf], bl);
                mma16816(acc[mf][2*np+1], ah[mf], bl + 2);
                mma16816(acc[mf][2*np],   al[mf], bh);
                mma16816(acc[mf][2*np+1], al[mf], bh + 2);
            }
        }
    }
}

// ---------------------------------------------------------------------------
// Projection GEMMs -> head-major fp16 (Q pre-scaled)
// ---------------------------------------------------------------------------
__global__ __launch_bounds__(256, 2) void proj_tc_kernel(
    const float* __restrict__ bq, const float* __restrict__ bk, const float* __restrict__ bv)
{
    extern __shared__ char smc[];
    const uint32_t smb = smem_u32(smc);

    const int z = blockIdx.z;
    const float* bias = (z == 0) ? bq : (z == 1) ? bk : bv;
    const __nv_bfloat16* XH = g_insh + (size_t)z * M_ * HID_;
    const __nv_bfloat16* XL = g_insl + (size_t)z * M_ * HID_;
    const __nv_bfloat16* WH = g_wh + (size_t)z * HID_ * HDK_;
    const __nv_bfloat16* WL = g_wl + (size_t)z * HID_ * HDK_;
    __half* Y = (z == 0) ? g_q16 : (z == 1) ? g_k16 : g_v16;
    const float osc = (z == 0) ? SCALE_ : 1.0f;

    const int m0 = blockIdx.y * 128, n0 = blockIdx.x * 128;
    float acc[2][8][4] = {};
    gemm_main(XH, XL, WH, WL, m0, n0, smb, acc);

    const int lane = threadIdx.x & 31, warp = threadIdx.x >> 5;
    const int m0w = (warp >> 1) * 32, n0w = (warp & 1) * 64;
    #pragma unroll
    for (int mf = 0; mf < 2; ++mf) {
        #pragma unroll
        for (int nf = 0; nf < 8; ++nf) {
            const int mr = m0 + m0w + mf * 16 + (lane >> 2);
            const int nn = n0 + n0w + nf * 8 + (lane & 3) * 2;
            const int hh = nn >> 6, dk = nn & 63;
            const float b0 = bias[nn], b1 = bias[nn + 1];
            #pragma unroll
            for (int rr = 0; rr < 2; ++rr) {
                const int m = mr + rr * 8;
                const int bb = m >> 11, ss = m & 2047;
                float v0 = (acc[mf][nf][2*rr]     + b0) * osc;
                float v1 = (acc[mf][nf][2*rr + 1] + b1) * osc;
                size_t idx = (((size_t)bb * H_ + hh) * S_ + ss) * DK_ + dk;
                *(uint32_t*)&Y[idx] = pack_h2(v0, v1);
            }
        }
    }
}

// ---------------------------------------------------------------------------
// fp16 HMMA flash attention, fixed-reference softmax (m = 0).
// CTA = 64 q-rows of one (b,h), 128 threads (4 warps x m16).
// 64-key tiles; Q single fp16 (regs), K/V single fp16 in 3-stage smem ring.
// Stage: KH[64][72] 9216 | VH[64][72] 9216 = 18432; x3 = 55296.
// ---------------------------------------------------------------------------
#define KV_ST 18432
#define ATTN_SMEM (3 * KV_ST)

__device__ __forceinline__ void cp_kv(uint32_t dstbase,
    const __half* __restrict__ K16, const __half* __restrict__ V16,
    int k0, int tid)
{
    #pragma unroll
    for (int i = 0; i < 8; i++) {
        int idx = tid + i * 128;                 // 1024 chunks (2 mats x 512)
        int mat = idx >> 9, rem = idx & 511;
        int row = rem >> 3, c8 = (rem & 7) * 8;
        const __half* src = ((mat == 0) ? K16 : V16) + (size_t)(k0 + row) * DK_ + c8;
        uint32_t dst = dstbase + mat * 9216 + (uint32_t)(row * 72 + c8) * 2;
        CP_ASYNC16(dst, src);
    }
}

__global__ __launch_bounds__(128, 4) void attn_tc_kernel(
    const float* __restrict__ attn_bias, const int* __restrict__ mask)
{
    extern __shared__ char sm[];
    const uint32_t smb = smem_u32(sm);
    const int tid = threadIdx.x;
    const int lane = tid & 31, warp = tid >> 5;
    const int g = lane >> 2, tig = lane & 3;
    const int q0 = blockIdx.x * 64;
    const int h = blockIdx.y, b = blockIdx.z;

    const size_t hb = ((size_t)b * H_ + h) * S_ * DK_;
    const __half* Qg  = g_q16 + hb + (size_t)q0 * DK_;
    const __half* K16 = g_k16 + hb;
    const __half* V16 = g_v16 + hb;

    // Q fragments -> registers (mma A-frag layout), loaded once
    uint32_t qh[4][4];
    {
        const int r0 = warp * 16 + g;
        #pragma unroll
        for (int ks = 0; ks < 4; ks++) {
            const int c = ks * 16 + tig * 2;
            qh[ks][0] = *(const uint32_t*)&Qg[(size_t)r0 * DK_ + c];
            qh[ks][1] = *(const uint32_t*)&Qg[(size_t)(r0 + 8) * DK_ + c];
            qh[ks][2] = *(const uint32_t*)&Qg[(size_t)r0 * DK_ + c + 8];
            qh[ks][3] = *(const uint32_t*)&Qg[(size_t)(r0 + 8) * DK_ + c + 8];
        }
    }

    // Prologue: tiles 0,1 -> stages 0,1
    cp_kv(smb, K16, V16, 0, tid);
    CP_COMMIT();
    cp_kv(smb + KV_ST, K16, V16, 64, tid);
    CP_COMMIT();

    const int qr0 = q0 + warp * 16 + g;
    const float* biasrow = attn_bias + (((size_t)b * H_ + h) * S_ + qr0) * S_;
    const float* mfb = g_maskf + b * S_;

    float oa[8][4] = {};
    float lsum0 = 0.f, lsum8 = 0.f;

    const uint32_t kbase = (uint32_t)(((lane & 7) + ((lane & 16) >> 1)) * 72
                                      + (lane & 8)) * 2;
    const uint32_t vbase = (uint32_t)((lane & 15) * 72 + (lane >> 4) * 8) * 2;

    int sidx = 0;
    for (int t = 0; t < 32; ++t) {
        const int k0 = t * 64;
        const uint32_t sb = smb + (uint32_t)sidx * KV_ST;

        // bias/mask prefetch into registers (overlaps outstanding cp.async)
        float2 b0r[8], b1r[8], mr[8];
        #pragma unroll
        for (int nf = 0; nf < 8; nf++) {
            int c = k0 + 8 * nf + 2 * tig;
            b0r[nf] = *(const float2*)&biasrow[c];
            b1r[nf] = *(const float2*)&biasrow[c + 8 * S_];
            mr[nf]  = *(const float2*)&mfb[c];
        }

        if (t + 1 < 32) { CP_WAIT1(); } else { CP_WAIT0(); }
        __syncthreads();

        if (t + 2 < 32) {
            const int pidx = (sidx + 2 >= 3) ? sidx - 1 : sidx + 2;
            cp_kv(smb + (uint32_t)pidx * KV_ST, K16, V16, (t + 2) * 64, tid);
            CP_COMMIT();
        }
        sidx = (sidx + 1 >= 3) ? 0 : sidx + 1;

        // S = Q K^T (Q single fp16)
        float sa[8][4];
        #pragma unroll
        for (int i = 0; i < 8; i++)
            #pragma unroll
            for (int j = 0; j < 4; j++) sa[i][j] = 0.f;

        #pragma unroll
        for (int ks = 0; ks < 4; ks++) {
            #pragma unroll
            for (int nf = 0; nf < 4; nf++) {
                uint32_t kaddr = sb + kbase + (uint32_t)(nf * 16 * 72 + ks * 16) * 2;
                uint32_t kh4[4];
                lds4(kh4, kaddr);
                mma16816h(sa[2*nf],   qh[ks], kh4);
                mma16816h(sa[2*nf+1], qh[ks], kh4 + 2);
            }
        }

        // mask-select + bias; p = exp(s) fixed-ref; accumulate row sums
        #pragma unroll
        for (int nf = 0; nf < 8; nf++) {
            sa[nf][0] = expf_fast(((mr[nf].x != 0.f) ? sa[nf][0] : NEG_) + b0r[nf].x);
            sa[nf][1] = expf_fast(((mr[nf].y != 0.f) ? sa[nf][1] : NEG_) + b0r[nf].y);
            sa[nf][2] = expf_fast(((mr[nf].x != 0.f) ? sa[nf][2] : NEG_) + b1r[nf].x);
            sa[nf][3] = expf_fast(((mr[nf].y != 0.f) ? sa[nf][3] : NEG_) + b1r[nf].y);
            lsum0 += sa[nf][0] + sa[nf][1];
            lsum8 += sa[nf][2] + sa[nf][3];
        }

        // O += P V (P single fp16, V single fp16)
        #pragma unroll
        for (int ks2 = 0; ks2 < 4; ks2++) {
            uint32_t ph[4];
            ph[0] = pack_h2(sa[2*ks2][0],   sa[2*ks2][1]);
            ph[1] = pack_h2(sa[2*ks2][2],   sa[2*ks2][3]);
            ph[2] = pack_h2(sa[2*ks2+1][0], sa[2*ks2+1][1]);
            ph[3] = pack_h2(sa[2*ks2+1][2], sa[2*ks2+1][3]);
            #pragma unroll
            for (int nf4 = 0; nf4 < 4; nf4++) {
                uint32_t vaddr = sb + 9216 + vbase
                               + (uint32_t)(ks2 * 16 * 72 + nf4 * 16) * 2;
                uint32_t vh4[4];
                lds4t(vh4, vaddr);
                mma16816h(oa[2*nf4],   ph, vh4);
                mma16816h(oa[2*nf4+1], ph, vh4 + 2);
            }
        }
    }

    // final row-sum reduce
    lsum0 += __shfl_xor_sync(0xffffffffu, lsum0, 1);
    lsum0 += __shfl_xor_sync(0xffffffffu, lsum0, 2);
    lsum8 += __shfl_xor_sync(0xffffffffu, lsum8, 1);
    lsum8 += __shfl_xor_sync(0xffffffffu, lsum8, 2);

    // epilogue: normalize, q-mask, write bf16 hi/lo token-major xh
    float qm0 = (mask[b * S_ + qr0]     != 0) ? 1.f : 0.f;
    float qm8 = (mask[b * S_ + qr0 + 8] != 0) ? 1.f : 0.f;
    float inv0 = qm0 / lsum0, inv8 = qm8 / lsum8;
    #pragma unroll
    for (int nf = 0; nf < 8; nf++) {
        int col = h * DK_ + 8 * nf + 2 * tig;
        uint32_t hi, lo;
        split2(oa[nf][0] * inv0, oa[nf][1] * inv0, hi, lo);
        size_t i0 = (size_t)(b * S_ + qr0) * HDK_ + col;
        *(uint32_t*)&g_xhh[i0] = hi;
        *(uint32_t*)&g_xhl[i0] = lo;
        split2(oa[nf][2] * inv8, oa[nf][3] * inv8, hi, lo);
        size_t i8 = (size_t)(b * S_ + qr0 + 8) * HDK_ + col;
        *(uint32_t*)&g_xhh[i8] = hi;
        *(uint32_t*)&g_xhl[i8] = lo;
    }
}

// ---------------------------------------------------------------------------
// Output GEMM: out = xh @ Wo + bo
// ---------------------------------------------------------------------------
__global__ __launch_bounds__(256, 2) void out_tc_kernel(
    const float* __restrict__ bo, float* __restrict__ out)
{
    extern __shared__ char smc[];
    const uint32_t smb = smem_u32(smc);

    const __nv_bfloat16* WH = g_wh + (size_t)3 * HID_ * HDK_;
    const __nv_bfloat16* WL = g_wl + (size_t)3 * HID_ * HDK_;

    const int m0 = blockIdx.y * 128, n0 = blockIdx.x * 128;
    float acc[2][8][4] = {};
    gemm_main(g_xhh, g_xhl, WH, WL, m0, n0, smb, acc);

    const int lane = threadIdx.x & 31, warp = threadIdx.x >> 5;
    const int m0w = (warp >> 1) * 32, n0w = (warp & 1) * 64;
    #pragma unroll
    for (int mf = 0; mf < 2; ++mf) {
        #pragma unroll
        for (int nf = 0; nf < 8; ++nf) {
            const int mr = m0 + m0w + mf * 16 + (lane >> 2);
            const int nn = n0 + n0w + nf * 8 + (lane & 3) * 2;
            const float b0 = bo[nn], b1 = bo[nn + 1];
            *(float2*)&out[(size_t)mr * HDK_ + nn] =
                make_float2(acc[mf][nf][0] + b0, acc[mf][nf][1] + b1);
            *(float2*)&out[(size_t)(mr + 8) * HDK_ + nn] =
                make_float2(acc[mf][nf][2] + b0, acc[mf][nf][3] + b1);
        }
    }
}

// ---------------------------------------------------------------------------
extern "C" void kernel_launch(void* const* d_in, const int* in_sizes, int n_in,
                              void* d_out, int out_size)
{
    const float* q         = (const float*)d_in[0];
    const float* k         = (const float*)d_in[1];
    const float* v         = (const float*)d_in[2];
    const float* attn_bias = (const float*)d_in[3];
    const int*   mask      = (const int*)  d_in[4];
    const float* Wq        = (const float*)d_in[5];
    const float* bq        = (const float*)d_in[6];
    const float* Wk        = (const float*)d_in[7];
    const float* bk        = (const float*)d_in[8];
    const float* Wv        = (const float*)d_in[9];
    const float* bv        = (const float*)d_in[10];
    const float* Wo        = (const float*)d_in[11];
    const float* bo        = (const float*)d_in[12];
    float* out = (float*)d_out;

    static int configured = 0;
    if (!configured) {
        cudaFuncSetAttribute(proj_tc_kernel, cudaFuncAttributeMaxDynamicSharedMemorySize, GSM_BYTES);
        cudaFuncSetAttribute(out_tc_kernel,  cudaFuncAttributeMaxDynamicSharedMemorySize, GSM_BYTES);
        cudaFuncSetAttribute(attn_tc_kernel, cudaFuncAttributeMaxDynamicSharedMemorySize, ATTN_SMEM);
        configured = 1;
    }

    prep_kernel<<<dim3(M_ * HID_ / 4 / 256, 7), 256>>>(q, k, v, Wq, Wk, Wv, Wo);
    maskprep_kernel<<<(B_ * S_ + 255) / 256, 256>>>(mask);

    proj_tc_kernel<<<dim3(HDK_ / 128, M_ / 128, 3), 256, GSM_BYTES>>>(bq, bk, bv);

    attn_tc_kernel<<<dim3(S_ / 64, H_, B_), 128, ATTN_SMEM>>>(attn_bias, mask);

    out_tc_kernel<<<dim3(HDK_ / 128, M_ / 128), 256, GSM_BYTES>>>(bo, out);
}